// round 8
// baseline (speedup 1.0000x reference)
#include <cuda_runtime.h>
#include <cuda_fp16.h>
#include <cstdint>

// ---------------- problem constants ----------------
#define BATCH 8
#define CIN   512
#define HF    10
#define WF    25
#define HW    250          // HF*WF
#define CF    64
#define NANCH 2784         // total anchors N
#define MCOL  2783         // N-1
#define DF    640          // CF*HF
#define LDSC  2784         // padded scores row stride
#define KCAT  1280         // 2*DF
#define NINV  (NANCH*HF)   // 27840 mask entries
#define MROWS (BATCH*NANCH) // 22272
#define TSH   5120         // halves per smem tile (128 rows * 40 padded)
#define NSTAGE 2

// ---------------- scratch (device globals; no allocation allowed) ----------------
__device__ __align__(128) __half g_xh [(size_t)BATCH*HW*CIN];
__device__ __align__(128) __half g_xl [(size_t)BATCH*HW*CIN];
__device__ __align__(128) __half g_cwh[(size_t)CF*CIN];
__device__ __align__(128) __half g_cwl[(size_t)CF*CIN];
__device__ __align__(128) __half g_awh[(size_t)MCOL*DF];
__device__ __align__(128) __half g_awl[(size_t)MCOL*DF];
__device__ __align__(128) __half g_pfh[(size_t)BATCH*NANCH*DF];
__device__ __align__(128) __half g_pfl[(size_t)BATCH*NANCH*DF];
__device__ __align__(128) __half g_pth[(size_t)BATCH*DF*NANCH];
__device__ __align__(128) __half g_ptl[(size_t)BATCH*DF*NANCH];
__device__ __align__(128) __half g_prh[(size_t)BATCH*NANCH*NANCH];
__device__ __align__(128) __half g_prl[(size_t)BATCH*NANCH*NANCH];
__device__ __align__(128) __half g_afh[(size_t)BATCH*NANCH*DF];
__device__ __align__(128) __half g_afl[(size_t)BATCH*NANCH*DF];
__device__ __align__(128) __half g_wh [(size_t)75*KCAT];
__device__ __align__(128) __half g_wl [(size_t)75*KCAT];
__device__ __align__(128) float  g_b75[80];
__device__ __align__(128) float  g_head[(size_t)MROWS*75];
__device__ __align__(128) float  g_feat[(size_t)BATCH*HW*CF];
__device__ __align__(128) float  g_sc  [(size_t)BATCH*NANCH*LDSC];
__device__ unsigned char g_inv[NINV];

// ---------------- helpers ----------------
__device__ __forceinline__ uint32_t smem_u32(const void* p) {
    uint32_t a;
    asm("{ .reg .u64 t; cvta.to.shared.u64 t, %1; cvt.u32.u64 %0, t; }" : "=r"(a) : "l"(p));
    return a;
}
__device__ __forceinline__ void cp16(uint32_t dst, const void* src, int sz) {
    asm volatile("cp.async.cg.shared.global [%0], [%1], 16, %2;" :: "r"(dst), "l"(src), "r"(sz) : "memory");
}
#define CP_COMMIT() asm volatile("cp.async.commit_group;" ::: "memory")
#define CP_WAIT(n)  asm volatile("cp.async.wait_group %0;" :: "n"(n) : "memory")
#define LDSM4(R0,R1,R2,R3,ADDR) \
    asm volatile("ldmatrix.sync.aligned.m8n8.x4.shared.b16 {%0,%1,%2,%3}, [%4];" \
        : "=r"(R0), "=r"(R1), "=r"(R2), "=r"(R3) : "r"(ADDR))
#define HMMA(C,A,B0,B1) \
    asm volatile("mma.sync.aligned.m16n8k16.row.col.f32.f16.f16.f32 " \
        "{%0,%1,%2,%3}, {%4,%5,%6,%7}, {%8,%9}, {%0,%1,%2,%3};" \
        : "+f"((C)[0]), "+f"((C)[1]), "+f"((C)[2]), "+f"((C)[3]) \
        : "r"((A)[0]), "r"((A)[1]), "r"((A)[2]), "r"((A)[3]), "r"(B0), "r"(B1))

__device__ __forceinline__ void split16(float v, __half& h, __half& l) {
    h = __float2half_rn(v);
    l = __float2half_rn(v - __half2float(h));
}

// ================= fp16 split 3-pass HMMA GEMM =================
// C[m,n] = sum_k (Ah+Al)[m,k]*(Bh+Bl)[n,k] (NT), fp32 accumulate, Al*Bl dropped.
// CTA tile 128x128, BK=32, 2-stage cp.async, 8 warps (2x4), warp 64x32.
// LDSM issue is staggered by operand lifetime to interleave crossbar & tensor.
template<bool F16OUT>
__global__ __launch_bounds__(256, 2) void k_hmma(
    const __half* __restrict__ Ah, const __half* __restrict__ Al,
    const __half* __restrict__ A2h, const __half* __restrict__ A2l,
    int lda, int kSplit,
    const __half* __restrict__ Bh, const __half* __restrict__ Bl,
    int ldb, int nBrows,
    float* __restrict__ Cf, __half* __restrict__ Ch, __half* __restrict__ Cl,
    const float* __restrict__ bias,
    int ldc, int M, int Ncols, int nStages,
    size_t sA, size_t sB, size_t sC)
{
    extern __shared__ __align__(128) __half sm[];
    const int tid = threadIdx.x, lane = tid & 31, wid = tid >> 5;
    const int z = blockIdx.z;
    Ah += sA * z; Al += sA * z; A2h += sA * z; A2l += sA * z;
    Bh += sB * z; Bl += sB * z;
    const size_t cOff = sC * z;
    const int row0 = blockIdx.y * 128;
    const int col0 = blockIdx.x * 128;
    const int warpM = wid >> 2, warpN = wid & 3;

    float acc[4][4][4];
#pragma unroll
    for (int i = 0; i < 4; i++)
#pragma unroll
        for (int j = 0; j < 4; j++)
#pragma unroll
            for (int q = 0; q < 4; q++) acc[i][j][q] = 0.f;

    const uint32_t smb = smem_u32(sm);

    auto fill = [&](int s) {
        int k0 = s * 32;
        const __half *aH, *aL; int koff;
        if (k0 < kSplit) { aH = Ah;  aL = Al;  koff = k0; }
        else             { aH = A2h; aL = A2l; koff = k0 - kSplit; }
        uint32_t base = smb + (uint32_t)(s & 1) * (4 * TSH * 2);
#pragma unroll
        for (int l = 0; l < 2; l++) {
            int i = tid + l * 256;
            int r = i >> 2, c = (i & 3) * 8;
            uint32_t d = base + (uint32_t)(r * 40 + c) * 2;
            int okA = (row0 + r < M) ? 16 : 0;
            size_t oA = okA ? ((size_t)(row0 + r) * lda + koff + c) : 0;
            cp16(d,           aH + oA, okA);
            cp16(d + TSH * 2, aL + oA, okA);
            int okB = (col0 + r < nBrows) ? 16 : 0;
            size_t oB = okB ? ((size_t)(col0 + r) * ldb + k0 + c) : 0;
            cp16(d + 2 * TSH * 2, Bh + oB, okB);
            cp16(d + 3 * TSH * 2, Bl + oB, okB);
        }
    };

    fill(0); CP_COMMIT();

    for (int s = 0; s < nStages; s++) {
        if (s + 1 < nStages) { fill(s + 1); CP_COMMIT(); CP_WAIT(1); }
        else                 { CP_WAIT(0); }
        __syncthreads();

        uint32_t bA_h = smb + (uint32_t)(s & 1) * (4 * TSH * 2);
        uint32_t bA_l = bA_h + TSH * 2;
        uint32_t bB_h = bA_h + 2 * TSH * 2;
        uint32_t bB_l = bA_h + 3 * TSH * 2;
#pragma unroll
        for (int kk = 0; kk < 2; kk++) {
            const int k0 = kk * 16;
            uint32_t aoff = (uint32_t)(((warpM * 64 + (lane & 15)) * 40
                             + k0 + ((lane >> 4) << 3)) * 2);
            uint32_t boff = (uint32_t)(((warpN * 32 + ((lane >> 4) << 3) + (lane & 7)) * 40
                             + k0 + ((lane >> 3) & 1) * 8) * 2);
            // phase 0: only hi fragments
            uint32_t a_h[4][4], b_h[8];
#pragma unroll
            for (int i = 0; i < 4; i++)
                LDSM4(a_h[i][0], a_h[i][1], a_h[i][2], a_h[i][3], bA_h + aoff + i * 1280);
            LDSM4(b_h[0], b_h[1], b_h[2], b_h[3], bB_h + boff);
            LDSM4(b_h[4], b_h[5], b_h[6], b_h[7], bB_h + boff + 1280);
            // pass 1: Ah*Bh
#pragma unroll
            for (int i = 0; i < 4; i++)
#pragma unroll
                for (int j = 0; j < 4; j++)
                    HMMA(acc[i][j], a_h[i], b_h[2*j], b_h[2*j+1]);
            // phase 1: load b_l between passes (crossbar overlaps tensor)
            uint32_t b_l[8];
            LDSM4(b_l[0], b_l[1], b_l[2], b_l[3], bB_l + boff);
            LDSM4(b_l[4], b_l[5], b_l[6], b_l[7], bB_l + boff + 1280);
            // pass 2: Ah*Bl
#pragma unroll
            for (int i = 0; i < 4; i++)
#pragma unroll
                for (int j = 0; j < 4; j++)
                    HMMA(acc[i][j], a_h[i], b_l[2*j], b_l[2*j+1]);
            // phase 2: load a_l between passes
            uint32_t a_l[4][4];
#pragma unroll
            for (int i = 0; i < 4; i++)
                LDSM4(a_l[i][0], a_l[i][1], a_l[i][2], a_l[i][3], bA_l + aoff + i * 1280);
            // pass 3: Al*Bh
#pragma unroll
            for (int i = 0; i < 4; i++)
#pragma unroll
                for (int j = 0; j < 4; j++)
                    HMMA(acc[i][j], a_l[i], b_h[2*j], b_h[2*j+1]);
        }
        __syncthreads();
    }

    // epilogue: registers -> global
#pragma unroll
    for (int i = 0; i < 4; i++) {
        int gm0 = row0 + warpM * 64 + i * 16 + (lane >> 2);
#pragma unroll
        for (int j = 0; j < 4; j++) {
            int gn = col0 + warpN * 32 + j * 8 + 2 * (lane & 3);
            float b0 = 0.f, b1 = 0.f;
            if (bias) {
                if (gn     < Ncols) b0 = bias[gn];
                if (gn + 1 < Ncols) b1 = bias[gn + 1];
            }
#pragma unroll
            for (int h = 0; h < 2; h++) {
                int gm = gm0 + h * 8;
                if (gm >= M) continue;
                float c0 = acc[i][j][2*h]     + b0;
                float c1 = acc[i][j][2*h + 1] + b1;
                if (F16OUT) {
                    size_t o = cOff + (size_t)gm * ldc + gn;
                    if (gn < Ncols) { __half hh, ll; split16(c0, hh, ll); Ch[o] = hh; Cl[o] = ll; }
                    if (gn + 1 < Ncols) { __half hh, ll; split16(c1, hh, ll); Ch[o+1] = hh; Cl[o+1] = ll; }
                } else {
                    float* dst = Cf + cOff + (size_t)gm * ldc + gn;
                    if (gn     < Ncols) dst[0] = c0;
                    if (gn + 1 < Ncols) dst[1] = c1;
                }
            }
        }
    }
}

// ================= fused preprocessing (ONE launch) =================
#define PREP_NB 8486
__global__ void k_prep(const float* __restrict__ x,
                       const float* __restrict__ conv_w,
                       const float* __restrict__ attn_w,
                       const float* __restrict__ cls_w,
                       const float* __restrict__ reg_w,
                       const float* __restrict__ cls_b,
                       const float* __restrict__ reg_b,
                       const unsigned int* __restrict__ invw) {
    int bid = blockIdx.x;
    int tid = threadIdx.x;
    if (bid < 1024) {
        __shared__ float tile[32][33];
        int b  = bid >> 7;
        int rem = bid & 127;
        int p0 = (rem & 7) * 32;
        int c0 = (rem >> 3) * 32;
        int tx = tid & 31, ty = tid >> 5;
        for (int i = ty; i < 32; i += 8) {
            int c = c0 + i, p = p0 + tx;
            float v = 0.f;
            if (p < HW) v = x[((size_t)b*CIN + c)*HW + p];
            tile[i][tx] = v;
        }
        __syncthreads();
        for (int i = ty; i < 32; i += 8) {
            int p = p0 + i, c = c0 + tx;
            if (p < HW) {
                float v = tile[tx][i];
                __half h, l; split16(v, h, l);
                size_t o = ((size_t)b*HW + p)*CIN + c;
                g_xh[o] = h; g_xl[o] = l;
            }
        }
    } else if (bid < 1152) {
        int i = (bid - 1024) * 256 + tid;
        if (i < CF*CIN) { __half h, l; split16(conv_w[i], h, l); g_cwh[i] = h; g_cwl[i] = l; }
    } else if (bid < 8110) {
        int i = (bid - 1152) * 256 + tid;
        if (i < MCOL*DF) { __half h, l; split16(attn_w[i], h, l); g_awh[i] = h; g_awl[i] = l; }
    } else if (bid < 8485) {
        int i = (bid - 8110) * 256 + tid;
        if (i < 75*KCAT) {
            float v = (i < 2*KCAT) ? cls_w[i] : reg_w[i - 2*KCAT];
            __half h, l; split16(v, h, l);
            g_wh[i] = h; g_wl[i] = l;
        }
    } else {
        __shared__ int s_float, s_byte;
        if (tid == 0) { s_float = 0; s_byte = 0; }
        __syncthreads();
        for (int i = tid; i < NINV/4; i += 256) {
            unsigned int v = invw[i];
            if (v == 0x3F800000u) atomicOr(&s_float, 1);
            else if (v & 0xFFFFFF00u) atomicOr(&s_byte, 1);
        }
        __syncthreads();
        int wordmode = (s_float || !s_byte) ? 1 : 0;
        const unsigned char* invb = (const unsigned char*)invw;
        for (int i = tid; i < NINV; i += 256)
            g_inv[i] = wordmode ? (invw[i] ? 1 : 0) : (invb[i] ? 1 : 0);
        if (tid < 2) g_b75[tid] = cls_b[tid];
        else if (tid < 75) g_b75[tid] = reg_b[tid - 2];
    }
}

// gather
__global__ void k_gather16(const int* __restrict__ cut_xs) {
    size_t idx = (size_t)blockIdx.x * 256 + threadIdx.x;
    const size_t total = (size_t)BATCH*NANCH*DF;
    if (idx >= total) return;
    int d = (int)(idx % DF);
    size_t r = idx / DF;
    int n = (int)(r % NANCH);
    int b = (int)(r / NANCH);
    int c = d / HF, h = d % HF;
    int xs = cut_xs[n*HF + h];
    float v = 0.f;
    if (!g_inv[n*HF + h])
        v = g_feat[(((size_t)b*HF + h)*WF + xs)*CF + c];
    __half hh, ll; split16(v, hh, ll);
    g_pfh[idx] = hh; g_pfl[idx] = ll;
}

// pf16 transpose
__global__ void k_pfT16() {
    __shared__ __half tile[32][33];
    int zb = blockIdx.z;
    int b = zb % BATCH;
    const __half* src = (zb < BATCH) ? g_pfh : g_pfl;
    __half*       dst = (zb < BATCH) ? g_pth : g_ptl;
    src += (size_t)b*NANCH*DF;
    dst += (size_t)b*DF*NANCH;
    int n0 = blockIdx.x * 32;
    int d0 = blockIdx.y * 32;
    for (int i = threadIdx.y; i < 32; i += 8)
        tile[i][threadIdx.x] = src[(size_t)(n0 + i)*DF + d0 + threadIdx.x];
    __syncthreads();
    for (int i = threadIdx.y; i < 32; i += 8)
        dst[(size_t)(d0 + i)*NANCH + n0 + threadIdx.x] = tile[threadIdx.x][i];
}

// softmax
__global__ __launch_bounds__(256) void k_softmax(float* __restrict__ attn_out) {
    int row = blockIdx.x;
    int i = row % NANCH;
    const float* s = g_sc + (size_t)row * LDSC;
    __shared__ float buf[MCOL];
    __shared__ float red[8];
    int tid = threadIdx.x;

    float mx = -1e30f;
    for (int m = tid; m < MCOL; m += 256) { float v = s[m]; buf[m] = v; mx = fmaxf(mx, v); }
#pragma unroll
    for (int o = 16; o > 0; o >>= 1) mx = fmaxf(mx, __shfl_xor_sync(0xffffffffu, mx, o));
    if ((tid & 31) == 0) red[tid >> 5] = mx;
    __syncthreads();
    float mall = red[0];
#pragma unroll
    for (int w = 1; w < 8; w++) mall = fmaxf(mall, red[w]);

    float sum = 0.f;
    for (int m = tid; m < MCOL; m += 256) { float e = __expf(buf[m] - mall); buf[m] = e; sum += e; }
#pragma unroll
    for (int o = 16; o > 0; o >>= 1) sum += __shfl_xor_sync(0xffffffffu, sum, o);
    __syncthreads();
    if ((tid & 31) == 0) red[tid >> 5] = sum;
    __syncthreads();
    float total = 0.f;
#pragma unroll
    for (int w = 0; w < 8; w++) total += red[w];
    float inv = 1.f / total;

    float* out = attn_out + (size_t)row * NANCH;
    __half* oh = g_prh + (size_t)row * NANCH;
    __half* ol = g_prl + (size_t)row * NANCH;
    for (int m = tid; m < MCOL; m += 256) {
        int j = m + (m >= i);
        float v = buf[m] * inv;
        out[j] = v;
        __half h, l; split16(v, h, l);
        oh[j] = h; ol[j] = l;
    }
    if (tid == 0) { out[i] = 0.f; oh[i] = __float2half(0.f); ol[i] = __float2half(0.f); }
}

// finalize
__global__ void k_finalize(const float* __restrict__ anchors,
                           float* __restrict__ out_cls, float* __restrict__ out_lanes) {
    size_t idx = (size_t)blockIdx.x * 256 + threadIdx.x;
    const size_t total = (size_t)MROWS * 79;
    if (idx >= total) return;
    int c = (int)(idx % 79);
    int gr = (int)(idx / 79);
    int n = gr % NANCH;
    if (c < 2) {
        out_cls[(size_t)gr*2 + c] = g_head[(size_t)gr*75 + c];
    } else {
        int lc = c - 2;
        float v;
        if (lc < 4)       v = anchors[(size_t)n*77 + lc];
        else if (lc == 4) v = g_head[(size_t)gr*75 + 2];
        else              v = anchors[(size_t)n*77 + lc] + g_head[(size_t)gr*75 + lc - 2];
        out_lanes[(size_t)gr*77 + lc] = v;
    }
}

// ---------------- launch ----------------
extern "C" void kernel_launch(void* const* d_in, const int* in_sizes, int n_in,
                              void* d_out, int out_size) {
    const void* ptr[12];
    for (int i = 0; i < 12 && i < n_in; i++) ptr[i] = d_in[i];
    {
        int seen27840 = 0;
        for (int i = 0; i < n_in; i++) {
            switch (in_sizes[i]) {
                case 1024000: ptr[0]  = d_in[i]; break; // x
                case 32768:   ptr[1]  = d_in[i]; break; // conv_w
                case 64:      ptr[2]  = d_in[i]; break; // conv_b
                case 1781120: ptr[3]  = d_in[i]; break; // attn_w
                case 2783:    ptr[4]  = d_in[i]; break; // attn_b
                case 2560:    ptr[5]  = d_in[i]; break; // cls_w
                case 2:       ptr[6]  = d_in[i]; break; // cls_b
                case 93440:   ptr[7]  = d_in[i]; break; // reg_w
                case 73:      ptr[8]  = d_in[i]; break; // reg_b
                case 214368:  ptr[9]  = d_in[i]; break; // anchors
                case 27840:
                    if (seen27840 == 0) ptr[10] = d_in[i];
                    else                ptr[11] = d_in[i];
                    seen27840++;
                    break;
                default: break;
            }
        }
    }
    const float* x        = (const float*)ptr[0];
    const float* conv_w   = (const float*)ptr[1];
    const float* conv_b   = (const float*)ptr[2];
    const float* attn_w   = (const float*)ptr[3];
    const float* attn_b   = (const float*)ptr[4];
    const float* cls_w    = (const float*)ptr[5];
    const float* cls_b    = (const float*)ptr[6];
    const float* reg_w    = (const float*)ptr[7];
    const float* reg_b    = (const float*)ptr[8];
    const float* anchors  = (const float*)ptr[9];
    const int*   cut_xs   = (const int*)ptr[10];
    const void*  invalid  = ptr[11];

    float* out      = (float*)d_out;
    float* o_cls    = out;
    float* o_lanes  = out + (size_t)MROWS*2;
    float* o_attn   = out + (size_t)MROWS*79;

    __half *xh,*xl,*cwh,*cwl,*awh,*awl,*pfh,*pfl,*pth,*ptl,*prh,*prl,*afh,*afl,*wh,*wl;
    float *b75,*head,*feat,*sc;
    cudaGetSymbolAddress((void**)&xh, g_xh);   cudaGetSymbolAddress((void**)&xl, g_xl);
    cudaGetSymbolAddress((void**)&cwh, g_cwh); cudaGetSymbolAddress((void**)&cwl, g_cwl);
    cudaGetSymbolAddress((void**)&awh, g_awh); cudaGetSymbolAddress((void**)&awl, g_awl);
    cudaGetSymbolAddress((void**)&pfh, g_pfh); cudaGetSymbolAddress((void**)&pfl, g_pfl);
    cudaGetSymbolAddress((void**)&pth, g_pth); cudaGetSymbolAddress((void**)&ptl, g_ptl);
    cudaGetSymbolAddress((void**)&prh, g_prh); cudaGetSymbolAddress((void**)&prl, g_prl);
    cudaGetSymbolAddress((void**)&afh, g_afh); cudaGetSymbolAddress((void**)&afl, g_afl);
    cudaGetSymbolAddress((void**)&wh, g_wh);   cudaGetSymbolAddress((void**)&wl, g_wl);
    cudaGetSymbolAddress((void**)&b75, g_b75); cudaGetSymbolAddress((void**)&head, g_head);
    cudaGetSymbolAddress((void**)&feat, g_feat); cudaGetSymbolAddress((void**)&sc, g_sc);

    const int SMEM = NSTAGE * 4 * TSH * 2;   // 81920 bytes
    cudaFuncSetAttribute(k_hmma<false>, cudaFuncAttributeMaxDynamicSharedMemorySize, SMEM);
    cudaFuncSetAttribute(k_hmma<true>,  cudaFuncAttributeMaxDynamicSharedMemorySize, SMEM);

    // launch 0: fused prep
    k_prep<<<PREP_NB, 256>>>(x, conv_w, attn_w, cls_w, reg_w, cls_b, reg_b,
                             (const unsigned int*)invalid);

    // launch 1: conv
    k_hmma<false><<<dim3(1, 16, 1), 256, SMEM>>>(
        xh, xl, xh, xl, CIN, 1 << 28,
        cwh, cwl, CIN, CF,
        feat, nullptr, nullptr, conv_b,
        CF, BATCH*HW, CF, CIN/32, 0, 0, 0);

    // launch 2: gather
    {
        size_t total = (size_t)BATCH*NANCH*DF;
        k_gather16<<<(unsigned)((total + 255)/256), 256>>>(cut_xs);
    }

    // launch 3 (ncu-captured): scores
    k_hmma<false><<<dim3(22, 22, BATCH), 256, SMEM>>>(
        pfh, pfl, pfh, pfl, DF, 1 << 28,
        awh, awl, DF, MCOL,
        sc, nullptr, nullptr, attn_b,
        LDSC, NANCH, MCOL, DF/32,
        (size_t)NANCH*DF, 0, (size_t)NANCH*LDSC);

    // launch 4: softmax
    k_softmax<<<BATCH*NANCH, 256>>>(o_attn);

    // launch 5: pf transpose
    k_pfT16<<<dim3(NANCH/32, DF/32, 2*BATCH), dim3(32, 8)>>>();

    // launch 6: att_feats
    k_hmma<true><<<dim3(5, 22, BATCH), 256, SMEM>>>(
        prh, prl, prh, prl, NANCH, 1 << 28,
        pth, ptl, NANCH, DF,
        nullptr, afh, afl, nullptr,
        DF, NANCH, DF, NANCH/32,
        (size_t)NANCH*NANCH, (size_t)DF*NANCH, (size_t)NANCH*DF);

    // launch 7: head
    k_hmma<false><<<dim3(1, MROWS/128, 1), 256, SMEM>>>(
        afh, afl, pfh, pfl, DF, DF,
        wh, wl, KCAT, 75,
        head, nullptr, nullptr, b75,
        75, MROWS, 75, KCAT/32, 0, 0, 0);

    // launch 8: finalize
    {
        size_t total = (size_t)MROWS * 79;
        k_finalize<<<(unsigned)((total + 255)/256), 256>>>(anchors, o_cls, o_lanes);
    }
}

// round 9
// speedup vs baseline: 1.3386x; 1.3386x over previous
#include <cuda_runtime.h>
#include <cuda_fp16.h>
#include <cstdint>

// ---------------- problem constants ----------------
#define BATCH 8
#define CIN   512
#define HF    10
#define WF    25
#define HW    250          // HF*WF
#define CF    64
#define NANCH 2784         // total anchors N
#define MCOL  2783         // N-1
#define DF    640          // CF*HF
#define LDSC  2784         // padded scores row stride
#define KCAT  1280         // 2*DF
#define NINV  (NANCH*HF)   // 27840 mask entries
#define MROWS (BATCH*NANCH) // 22272
#define TSH   5120         // halves per smem tile (128 rows * 40 padded)

// ---------------- scratch (device globals; no allocation allowed) ----------------
__device__ __align__(128) __half g_xh [(size_t)BATCH*HW*CIN];
__device__ __align__(128) __half g_xl [(size_t)BATCH*HW*CIN];
__device__ __align__(128) __half g_cwh[(size_t)CF*CIN];
__device__ __align__(128) __half g_cwl[(size_t)CF*CIN];
__device__ __align__(128) __half g_awh[(size_t)MCOL*DF];
__device__ __align__(128) __half g_awl[(size_t)MCOL*DF];
__device__ __align__(128) __half g_pfh[(size_t)BATCH*NANCH*DF];
__device__ __align__(128) __half g_pfl[(size_t)BATCH*NANCH*DF];
__device__ __align__(128) __half g_pth[(size_t)BATCH*DF*NANCH];
__device__ __align__(128) __half g_ptl[(size_t)BATCH*DF*NANCH];
__device__ __align__(128) __half g_prh[(size_t)BATCH*NANCH*NANCH];  // softmax probs hi
__device__ __align__(128) __half g_afh[(size_t)BATCH*NANCH*DF];
__device__ __align__(128) __half g_afl[(size_t)BATCH*NANCH*DF];
__device__ __align__(128) __half g_wh [(size_t)75*KCAT];
__device__ __align__(128) __half g_wl [(size_t)75*KCAT];
__device__ __align__(128) float  g_b75[80];
__device__ __align__(128) float  g_head[(size_t)MROWS*75];
__device__ __align__(128) float  g_feat[(size_t)BATCH*HW*CF];
__device__ __align__(128) float  g_sc  [(size_t)BATCH*NANCH*LDSC];
__device__ unsigned char g_inv[NINV];

// ---------------- helpers ----------------
__device__ __forceinline__ uint32_t smem_u32(const void* p) {
    uint32_t a;
    asm("{ .reg .u64 t; cvta.to.shared.u64 t, %1; cvt.u32.u64 %0, t; }" : "=r"(a) : "l"(p));
    return a;
}
__device__ __forceinline__ void cp16(uint32_t dst, const void* src, int sz) {
    asm volatile("cp.async.ca.shared.global [%0], [%1], 16, %2;" :: "r"(dst), "l"(src), "r"(sz) : "memory");
}
#define CP_COMMIT() asm volatile("cp.async.commit_group;" ::: "memory")
#define CP_WAIT(n)  asm volatile("cp.async.wait_group %0;" :: "n"(n) : "memory")
#define LDSM4(R0,R1,R2,R3,ADDR) \
    asm volatile("ldmatrix.sync.aligned.m8n8.x4.shared.b16 {%0,%1,%2,%3}, [%4];" \
        : "=r"(R0), "=r"(R1), "=r"(R2), "=r"(R3) : "r"(ADDR))
#define HMMA(C,A,B0,B1) \
    asm volatile("mma.sync.aligned.m16n8k16.row.col.f32.f16.f16.f32 " \
        "{%0,%1,%2,%3}, {%4,%5,%6,%7}, {%8,%9}, {%0,%1,%2,%3};" \
        : "+f"((C)[0]), "+f"((C)[1]), "+f"((C)[2]), "+f"((C)[3]) \
        : "r"((A)[0]), "r"((A)[1]), "r"((A)[2]), "r"((A)[3]), "r"(B0), "r"(B1))

__device__ __forceinline__ void split16(float v, __half& h, __half& l) {
    h = __float2half_rn(v);
    l = __float2half_rn(v - __half2float(h));
}

// ================= fp16 split HMMA GEMM =================
// PASSES==3: C = Ah*Bh + Ah*Bl + Al*Bh  (2-stage pipeline, 4 tiles/stage)
// PASSES==2: C = Ah*Bh + Ah*Bl          (3-stage pipeline, 3 tiles/stage,
//                                        single __syncthreads per stage)
// CTA tile 128x128, BK=32, 8 warps (2x4), warp tile 64x32, fp32 accumulate.
template<int PASSES, bool F16OUT>
__global__ __launch_bounds__(256, 2) void k_hmma(
    const __half* __restrict__ Ah, const __half* __restrict__ Al,
    const __half* __restrict__ A2h, const __half* __restrict__ A2l,
    int lda, int kSplit,
    const __half* __restrict__ Bh, const __half* __restrict__ Bl,
    int ldb, int nBrows,
    float* __restrict__ Cf, __half* __restrict__ Ch, __half* __restrict__ Cl,
    const float* __restrict__ bias,
    int ldc, int M, int Ncols, int nStages,
    size_t sA, size_t sB, size_t sC)
{
    constexpr int TILES = (PASSES == 3) ? 4 : 3;
    constexpr int NST   = (PASSES == 3) ? 2 : 3;
    constexpr uint32_t STGB = (uint32_t)TILES * TSH * 2;

    extern __shared__ __align__(128) __half sm[];
    const int tid = threadIdx.x, lane = tid & 31, wid = tid >> 5;
    const int z = blockIdx.z;
    Ah += sA * z; Al += sA * z; A2h += sA * z; A2l += sA * z;
    Bh += sB * z; Bl += sB * z;
    const size_t cOff = sC * z;
    const int row0 = blockIdx.y * 128;
    const int col0 = blockIdx.x * 128;
    const int warpM = wid >> 2, warpN = wid & 3;

    float acc[4][4][4];
#pragma unroll
    for (int i = 0; i < 4; i++)
#pragma unroll
        for (int j = 0; j < 4; j++)
#pragma unroll
            for (int q = 0; q < 4; q++) acc[i][j][q] = 0.f;

    const uint32_t smb = smem_u32(sm);

    auto fill = [&](int s) {
        int k0 = s * 32;
        const __half *aH, *aL; int koff;
        if (k0 < kSplit) { aH = Ah;  aL = Al;  koff = k0; }
        else             { aH = A2h; aL = A2l; koff = k0 - kSplit; }
        uint32_t base = smb + (uint32_t)(s % NST) * STGB;
#pragma unroll
        for (int l = 0; l < 2; l++) {
            int i = tid + l * 256;
            int r = i >> 2, c = (i & 3) * 8;
            uint32_t d = base + (uint32_t)(r * 40 + c) * 2;
            int okA = (row0 + r < M) ? 16 : 0;
            size_t oA = okA ? ((size_t)(row0 + r) * lda + koff + c) : 0;
            cp16(d, aH + oA, okA);
            if (PASSES == 3) cp16(d + TSH * 2, aL + oA, okA);
            int okB = (col0 + r < nBrows) ? 16 : 0;
            size_t oB = okB ? ((size_t)(col0 + r) * ldb + k0 + c) : 0;
            cp16(d + (uint32_t)(TILES - 2) * TSH * 2, Bh + oB, okB);
            cp16(d + (uint32_t)(TILES - 1) * TSH * 2, Bl + oB, okB);
        }
    };

    auto compute = [&](int s) {
        uint32_t base = smb + (uint32_t)(s % NST) * STGB;
        uint32_t bA_h = base;
        uint32_t bA_l = base + TSH * 2;                      // valid only PASSES==3
        uint32_t bB_h = base + (uint32_t)(TILES - 2) * TSH * 2;
        uint32_t bB_l = base + (uint32_t)(TILES - 1) * TSH * 2;
#pragma unroll
        for (int kk = 0; kk < 2; kk++) {
            const int k0 = kk * 16;
            uint32_t aoff = (uint32_t)(((warpM * 64 + (lane & 15)) * 40
                             + k0 + ((lane >> 4) << 3)) * 2);
            uint32_t boff = (uint32_t)(((warpN * 32 + ((lane >> 4) << 3) + (lane & 7)) * 40
                             + k0 + ((lane >> 3) & 1) * 8) * 2);
            uint32_t a_h[4][4], b_h[8], b_l[8];
#pragma unroll
            for (int i = 0; i < 4; i++)
                LDSM4(a_h[i][0], a_h[i][1], a_h[i][2], a_h[i][3], bA_h + aoff + i * 1280);
            LDSM4(b_h[0], b_h[1], b_h[2], b_h[3], bB_h + boff);
            LDSM4(b_h[4], b_h[5], b_h[6], b_h[7], bB_h + boff + 1280);
            LDSM4(b_l[0], b_l[1], b_l[2], b_l[3], bB_l + boff);
            LDSM4(b_l[4], b_l[5], b_l[6], b_l[7], bB_l + boff + 1280);
            // pass 1: Ah*Bh
#pragma unroll
            for (int i = 0; i < 4; i++)
#pragma unroll
                for (int j = 0; j < 4; j++)
                    HMMA(acc[i][j], a_h[i], b_h[2*j], b_h[2*j+1]);
            // pass 2: Ah*Bl
#pragma unroll
            for (int i = 0; i < 4; i++)
#pragma unroll
                for (int j = 0; j < 4; j++)
                    HMMA(acc[i][j], a_h[i], b_l[2*j], b_l[2*j+1]);
            if (PASSES == 3) {
                uint32_t a_l[4][4];
#pragma unroll
                for (int i = 0; i < 4; i++)
                    LDSM4(a_l[i][0], a_l[i][1], a_l[i][2], a_l[i][3], bA_l + aoff + i * 1280);
#pragma unroll
                for (int i = 0; i < 4; i++)
#pragma unroll
                    for (int j = 0; j < 4; j++)
                        HMMA(acc[i][j], a_l[i], b_h[2*j], b_h[2*j+1]);
            }
        }
    };

    if (PASSES == 3) {
        fill(0); CP_COMMIT();
        for (int s = 0; s < nStages; s++) {
            if (s + 1 < nStages) { fill(s + 1); CP_COMMIT(); CP_WAIT(1); }
            else                 { CP_WAIT(0); }
            __syncthreads();
            compute(s);
            __syncthreads();
        }
    } else {
        fill(0); CP_COMMIT();
        fill(1); CP_COMMIT();
        for (int s = 0; s < nStages; s++) {
            CP_WAIT(1);
            __syncthreads();
            if (s + 2 < nStages) fill(s + 2);
            CP_COMMIT();
            compute(s);
        }
    }

    // epilogue: registers -> global
#pragma unroll
    for (int i = 0; i < 4; i++) {
        int gm0 = row0 + warpM * 64 + i * 16 + (lane >> 2);
#pragma unroll
        for (int j = 0; j < 4; j++) {
            int gn = col0 + warpN * 32 + j * 8 + 2 * (lane & 3);
            float b0 = 0.f, b1 = 0.f;
            if (bias) {
                if (gn     < Ncols) b0 = bias[gn];
                if (gn + 1 < Ncols) b1 = bias[gn + 1];
            }
#pragma unroll
            for (int h = 0; h < 2; h++) {
                int gm = gm0 + h * 8;
                if (gm >= M) continue;
                float c0 = acc[i][j][2*h]     + b0;
                float c1 = acc[i][j][2*h + 1] + b1;
                if (F16OUT) {
                    size_t o = cOff + (size_t)gm * ldc + gn;
                    if (gn < Ncols) { __half hh, ll; split16(c0, hh, ll); Ch[o] = hh; Cl[o] = ll; }
                    if (gn + 1 < Ncols) { __half hh, ll; split16(c1, hh, ll); Ch[o+1] = hh; Cl[o+1] = ll; }
                } else {
                    float* dst = Cf + cOff + (size_t)gm * ldc + gn;
                    if (gn     < Ncols) dst[0] = c0;
                    if (gn + 1 < Ncols) dst[1] = c1;
                }
            }
        }
    }
}

// ================= fused preprocessing (ONE launch) =================
#define PREP_NB 8486
__global__ void k_prep(const float* __restrict__ x,
                       const float* __restrict__ conv_w,
                       const float* __restrict__ attn_w,
                       const float* __restrict__ cls_w,
                       const float* __restrict__ reg_w,
                       const float* __restrict__ cls_b,
                       const float* __restrict__ reg_b,
                       const unsigned int* __restrict__ invw) {
    int bid = blockIdx.x;
    int tid = threadIdx.x;
    if (bid < 1024) {
        __shared__ float tile[32][33];
        int b  = bid >> 7;
        int rem = bid & 127;
        int p0 = (rem & 7) * 32;
        int c0 = (rem >> 3) * 32;
        int tx = tid & 31, ty = tid >> 5;
        for (int i = ty; i < 32; i += 8) {
            int c = c0 + i, p = p0 + tx;
            float v = 0.f;
            if (p < HW) v = x[((size_t)b*CIN + c)*HW + p];
            tile[i][tx] = v;
        }
        __syncthreads();
        for (int i = ty; i < 32; i += 8) {
            int p = p0 + i, c = c0 + tx;
            if (p < HW) {
                float v = tile[tx][i];
                __half h, l; split16(v, h, l);
                size_t o = ((size_t)b*HW + p)*CIN + c;
                g_xh[o] = h; g_xl[o] = l;
            }
        }
    } else if (bid < 1152) {
        int i = (bid - 1024) * 256 + tid;
        if (i < CF*CIN) { __half h, l; split16(conv_w[i], h, l); g_cwh[i] = h; g_cwl[i] = l; }
    } else if (bid < 8110) {
        int i = (bid - 1152) * 256 + tid;
        if (i < MCOL*DF) { __half h, l; split16(attn_w[i], h, l); g_awh[i] = h; g_awl[i] = l; }
    } else if (bid < 8485) {
        int i = (bid - 8110) * 256 + tid;
        if (i < 75*KCAT) {
            float v = (i < 2*KCAT) ? cls_w[i] : reg_w[i - 2*KCAT];
            __half h, l; split16(v, h, l);
            g_wh[i] = h; g_wl[i] = l;
        }
    } else {
        __shared__ int s_float, s_byte;
        if (tid == 0) { s_float = 0; s_byte = 0; }
        __syncthreads();
        for (int i = tid; i < NINV/4; i += 256) {
            unsigned int v = invw[i];
            if (v == 0x3F800000u) atomicOr(&s_float, 1);
            else if (v & 0xFFFFFF00u) atomicOr(&s_byte, 1);
        }
        __syncthreads();
        int wordmode = (s_float || !s_byte) ? 1 : 0;
        const unsigned char* invb = (const unsigned char*)invw;
        for (int i = tid; i < NINV; i += 256)
            g_inv[i] = wordmode ? (invw[i] ? 1 : 0) : (invb[i] ? 1 : 0);
        if (tid < 2) g_b75[tid] = cls_b[tid];
        else if (tid < 75) g_b75[tid] = reg_b[tid - 2];
    }
}

// gather
__global__ void k_gather16(const int* __restrict__ cut_xs) {
    size_t idx = (size_t)blockIdx.x * 256 + threadIdx.x;
    const size_t total = (size_t)BATCH*NANCH*DF;
    if (idx >= total) return;
    int d = (int)(idx % DF);
    size_t r = idx / DF;
    int n = (int)(r % NANCH);
    int b = (int)(r / NANCH);
    int c = d / HF, h = d % HF;
    int xs = cut_xs[n*HF + h];
    float v = 0.f;
    if (!g_inv[n*HF + h])
        v = g_feat[(((size_t)b*HF + h)*WF + xs)*CF + c];
    __half hh, ll; split16(v, hh, ll);
    g_pfh[idx] = hh; g_pfl[idx] = ll;
}

// pf16 transpose
__global__ void k_pfT16() {
    __shared__ __half tile[32][33];
    int zb = blockIdx.z;
    int b = zb % BATCH;
    const __half* src = (zb < BATCH) ? g_pfh : g_pfl;
    __half*       dst = (zb < BATCH) ? g_pth : g_ptl;
    src += (size_t)b*NANCH*DF;
    dst += (size_t)b*DF*NANCH;
    int n0 = blockIdx.x * 32;
    int d0 = blockIdx.y * 32;
    for (int i = threadIdx.y; i < 32; i += 8)
        tile[i][threadIdx.x] = src[(size_t)(n0 + i)*DF + d0 + threadIdx.x];
    __syncthreads();
    for (int i = threadIdx.y; i < 32; i += 8)
        dst[(size_t)(d0 + i)*NANCH + n0 + threadIdx.x] = tile[threadIdx.x][i];
}

// softmax: writes f32 attn output and f16 (hi only) probs
__global__ __launch_bounds__(256) void k_softmax(float* __restrict__ attn_out) {
    int row = blockIdx.x;
    int i = row % NANCH;
    const float* s = g_sc + (size_t)row * LDSC;
    __shared__ float buf[MCOL];
    __shared__ float red[8];
    int tid = threadIdx.x;

    float mx = -1e30f;
    for (int m = tid; m < MCOL; m += 256) { float v = s[m]; buf[m] = v; mx = fmaxf(mx, v); }
#pragma unroll
    for (int o = 16; o > 0; o >>= 1) mx = fmaxf(mx, __shfl_xor_sync(0xffffffffu, mx, o));
    if ((tid & 31) == 0) red[tid >> 5] = mx;
    __syncthreads();
    float mall = red[0];
#pragma unroll
    for (int w = 1; w < 8; w++) mall = fmaxf(mall, red[w]);

    float sum = 0.f;
    for (int m = tid; m < MCOL; m += 256) { float e = __expf(buf[m] - mall); buf[m] = e; sum += e; }
#pragma unroll
    for (int o = 16; o > 0; o >>= 1) sum += __shfl_xor_sync(0xffffffffu, sum, o);
    __syncthreads();
    if ((tid & 31) == 0) red[tid >> 5] = sum;
    __syncthreads();
    float total = 0.f;
#pragma unroll
    for (int w = 0; w < 8; w++) total += red[w];
    float inv = 1.f / total;

    float* out = attn_out + (size_t)row * NANCH;
    __half* oh = g_prh + (size_t)row * NANCH;
    for (int m = tid; m < MCOL; m += 256) {
        int j = m + (m >= i);
        float v = buf[m] * inv;
        out[j] = v;
        oh[j] = __float2half_rn(v);
    }
    if (tid == 0) { out[i] = 0.f; oh[i] = __float2half(0.f); }
}

// finalize
__global__ void k_finalize(const float* __restrict__ anchors,
                           float* __restrict__ out_cls, float* __restrict__ out_lanes) {
    size_t idx = (size_t)blockIdx.x * 256 + threadIdx.x;
    const size_t total = (size_t)MROWS * 79;
    if (idx >= total) return;
    int c = (int)(idx % 79);
    int gr = (int)(idx / 79);
    int n = gr % NANCH;
    if (c < 2) {
        out_cls[(size_t)gr*2 + c] = g_head[(size_t)gr*75 + c];
    } else {
        int lc = c - 2;
        float v;
        if (lc < 4)       v = anchors[(size_t)n*77 + lc];
        else if (lc == 4) v = g_head[(size_t)gr*75 + 2];
        else              v = anchors[(size_t)n*77 + lc] + g_head[(size_t)gr*75 + lc - 2];
        out_lanes[(size_t)gr*77 + lc] = v;
    }
}

// ---------------- launch ----------------
extern "C" void kernel_launch(void* const* d_in, const int* in_sizes, int n_in,
                              void* d_out, int out_size) {
    const void* ptr[12];
    for (int i = 0; i < 12 && i < n_in; i++) ptr[i] = d_in[i];
    {
        int seen27840 = 0;
        for (int i = 0; i < n_in; i++) {
            switch (in_sizes[i]) {
                case 1024000: ptr[0]  = d_in[i]; break; // x
                case 32768:   ptr[1]  = d_in[i]; break; // conv_w
                case 64:      ptr[2]  = d_in[i]; break; // conv_b
                case 1781120: ptr[3]  = d_in[i]; break; // attn_w
                case 2783:    ptr[4]  = d_in[i]; break; // attn_b
                case 2560:    ptr[5]  = d_in[i]; break; // cls_w
                case 2:       ptr[6]  = d_in[i]; break; // cls_b
                case 93440:   ptr[7]  = d_in[i]; break; // reg_w
                case 73:      ptr[8]  = d_in[i]; break; // reg_b
                case 214368:  ptr[9]  = d_in[i]; break; // anchors
                case 27840:
                    if (seen27840 == 0) ptr[10] = d_in[i];
                    else                ptr[11] = d_in[i];
                    seen27840++;
                    break;
                default: break;
            }
        }
    }
    const float* x        = (const float*)ptr[0];
    const float* conv_w   = (const float*)ptr[1];
    const float* conv_b   = (const float*)ptr[2];
    const float* attn_w   = (const float*)ptr[3];
    const float* attn_b   = (const float*)ptr[4];
    const float* cls_w    = (const float*)ptr[5];
    const float* cls_b    = (const float*)ptr[6];
    const float* reg_w    = (const float*)ptr[7];
    const float* reg_b    = (const float*)ptr[8];
    const float* anchors  = (const float*)ptr[9];
    const int*   cut_xs   = (const int*)ptr[10];
    const void*  invalid  = ptr[11];

    float* out      = (float*)d_out;
    float* o_cls    = out;
    float* o_lanes  = out + (size_t)MROWS*2;
    float* o_attn   = out + (size_t)MROWS*79;

    __half *xh,*xl,*cwh,*cwl,*awh,*awl,*pfh,*pfl,*pth,*ptl,*prh,*afh,*afl,*wh,*wl;
    float *b75,*head,*feat,*sc;
    cudaGetSymbolAddress((void**)&xh, g_xh);   cudaGetSymbolAddress((void**)&xl, g_xl);
    cudaGetSymbolAddress((void**)&cwh, g_cwh); cudaGetSymbolAddress((void**)&cwl, g_cwl);
    cudaGetSymbolAddress((void**)&awh, g_awh); cudaGetSymbolAddress((void**)&awl, g_awl);
    cudaGetSymbolAddress((void**)&pfh, g_pfh); cudaGetSymbolAddress((void**)&pfl, g_pfl);
    cudaGetSymbolAddress((void**)&pth, g_pth); cudaGetSymbolAddress((void**)&ptl, g_ptl);
    cudaGetSymbolAddress((void**)&prh, g_prh);
    cudaGetSymbolAddress((void**)&afh, g_afh); cudaGetSymbolAddress((void**)&afl, g_afl);
    cudaGetSymbolAddress((void**)&wh, g_wh);   cudaGetSymbolAddress((void**)&wl, g_wl);
    cudaGetSymbolAddress((void**)&b75, g_b75); cudaGetSymbolAddress((void**)&head, g_head);
    cudaGetSymbolAddress((void**)&feat, g_feat); cudaGetSymbolAddress((void**)&sc, g_sc);

    const int SMEM3 = 2 * 4 * TSH * 2;   // 81920  (3-pass, 2-stage)
    const int SMEM2 = 3 * 3 * TSH * 2;   // 92160  (2-pass, 3-stage)
    cudaFuncSetAttribute(k_hmma<3,false>, cudaFuncAttributeMaxDynamicSharedMemorySize, SMEM3);
    cudaFuncSetAttribute(k_hmma<2,false>, cudaFuncAttributeMaxDynamicSharedMemorySize, SMEM2);
    cudaFuncSetAttribute(k_hmma<2,true>,  cudaFuncAttributeMaxDynamicSharedMemorySize, SMEM2);

    // launch 0: fused prep
    k_prep<<<PREP_NB, 256>>>(x, conv_w, attn_w, cls_w, reg_w, cls_b, reg_b,
                             (const unsigned int*)invalid);

    // launch 1: conv (3-pass, exact-ish: pf feeds cls directly)
    k_hmma<3,false><<<dim3(1, 16, 1), 256, SMEM3>>>(
        xh, xl, xh, xl, CIN, 1 << 28,
        cwh, cwl, CIN, CF,
        feat, nullptr, nullptr, conv_b,
        CF, BATCH*HW, CF, CIN/32, 0, 0, 0);

    // launch 2: gather
    {
        size_t total = (size_t)BATCH*NANCH*DF;
        k_gather16<<<(unsigned)((total + 255)/256), 256>>>(cut_xs);
    }

    // launch 3 (ncu-captured): scores — flattened M=22272, 2-pass
    // (dropping Al*Bh: abs score err ~1e-5, normalized away by softmax)
    k_hmma<2,false><<<dim3(22, MROWS/128, 1), 256, SMEM2>>>(
        pfh, pfl, pfh, pfl, DF, 1 << 28,
        awh, awl, DF, MCOL,
        sc, nullptr, nullptr, attn_b,
        LDSC, MROWS, MCOL, DF/32, 0, 0, 0);

    // launch 4: softmax
    k_softmax<<<BATCH*NANCH, 256>>>(o_attn);

    // launch 5: pf transpose
    k_pfT16<<<dim3(NANCH/32, DF/32, 2*BATCH), dim3(32, 8)>>>();

    // launch 6: att_feats — 2-pass (probs-lo dropped: ~2.4e-4 rel on att)
    k_hmma<2,true><<<dim3(5, 22, BATCH), 256, SMEM2>>>(
        prh, prh, prh, prh, NANCH, 1 << 28,
        pth, ptl, NANCH, DF,
        nullptr, afh, afl, nullptr,
        DF, NANCH, DF, NANCH/32,
        (size_t)NANCH*NANCH, (size_t)DF*NANCH, (size_t)NANCH*DF);

    // launch 7: head (3-pass)
    k_hmma<3,false><<<dim3(1, MROWS/128, 1), 256, SMEM3>>>(
        afh, afl, pfh, pfl, DF, DF,
        wh, wl, KCAT, 75,
        head, nullptr, nullptr, b75,
        75, MROWS, 75, KCAT/32, 0, 0, 0);

    // launch 8: finalize
    {
        size_t total = (size_t)MROWS * 79;
        k_finalize<<<(unsigned)((total + 255)/256), 256>>>(anchors, o_cls, o_lanes);
    }
}

// round 10
// speedup vs baseline: 1.7611x; 1.3157x over previous
#include <cuda_runtime.h>
#include <cuda_fp16.h>
#include <cstdint>

// ---------------- problem constants ----------------
#define BATCH 8
#define CIN   512
#define HF    10
#define WF    25
#define HW    250          // HF*WF
#define CF    64
#define NANCH 2784         // total anchors N
#define MCOL  2783         // N-1
#define DF    640          // CF*HF
#define LDSC  2784         // padded scores row stride
#define KCAT  1280         // 2*DF
#define NINV  (NANCH*HF)   // 27840 mask entries
#define MROWS (BATCH*NANCH) // 22272
#define TSH   5120         // halves per smem tile (128 rows * 40 padded)

// ---------------- scratch (device globals; no allocation allowed) ----------------
__device__ __align__(128) __half g_xh [(size_t)BATCH*HW*CIN];
__device__ __align__(128) __half g_xl [(size_t)BATCH*HW*CIN];
__device__ __align__(128) __half g_cwh[(size_t)CF*CIN];
__device__ __align__(128) __half g_cwl[(size_t)CF*CIN];
__device__ __align__(128) __half g_awh[(size_t)MCOL*DF];
__device__ __align__(128) __half g_pfh[(size_t)BATCH*NANCH*DF];
__device__ __align__(128) __half g_pfl[(size_t)BATCH*NANCH*DF];
__device__ __align__(128) __half g_pth[(size_t)BATCH*DF*NANCH];
__device__ __align__(128) __half g_prh[(size_t)BATCH*NANCH*NANCH];  // softmax probs hi
__device__ __align__(128) __half g_afh[(size_t)BATCH*NANCH*DF];
__device__ __align__(128) __half g_afl[(size_t)BATCH*NANCH*DF];
__device__ __align__(128) __half g_wh [(size_t)75*KCAT];
__device__ __align__(128) __half g_wl [(size_t)75*KCAT];
__device__ __align__(128) float  g_b75[80];
__device__ __align__(128) float  g_head[(size_t)MROWS*75];
__device__ __align__(128) float  g_feat[(size_t)BATCH*HW*CF];
__device__ __align__(128) float  g_sc  [(size_t)BATCH*NANCH*LDSC];
__device__ unsigned char g_inv[NINV];

// ---------------- helpers ----------------
__device__ __forceinline__ uint32_t smem_u32(const void* p) {
    uint32_t a;
    asm("{ .reg .u64 t; cvta.to.shared.u64 t, %1; cvt.u32.u64 %0, t; }" : "=r"(a) : "l"(p));
    return a;
}
__device__ __forceinline__ void cp16(uint32_t dst, const void* src, int sz) {
    asm volatile("cp.async.ca.shared.global [%0], [%1], 16, %2;" :: "r"(dst), "l"(src), "r"(sz) : "memory");
}
#define CP_COMMIT() asm volatile("cp.async.commit_group;" ::: "memory")
#define CP_WAIT(n)  asm volatile("cp.async.wait_group %0;" :: "n"(n) : "memory")
#define LDSM4(R0,R1,R2,R3,ADDR) \
    asm volatile("ldmatrix.sync.aligned.m8n8.x4.shared.b16 {%0,%1,%2,%3}, [%4];" \
        : "=r"(R0), "=r"(R1), "=r"(R2), "=r"(R3) : "r"(ADDR))
#define HMMA(C,A,B0,B1) \
    asm volatile("mma.sync.aligned.m16n8k16.row.col.f32.f16.f16.f32 " \
        "{%0,%1,%2,%3}, {%4,%5,%6,%7}, {%8,%9}, {%0,%1,%2,%3};" \
        : "+f"((C)[0]), "+f"((C)[1]), "+f"((C)[2]), "+f"((C)[3]) \
        : "r"((A)[0]), "r"((A)[1]), "r"((A)[2]), "r"((A)[3]), "r"(B0), "r"(B1))

__device__ __forceinline__ void split16(float v, __half& h, __half& l) {
    h = __float2half_rn(v);
    l = __float2half_rn(v - __half2float(h));
}

// ================= fp16 split HMMA GEMM =================
// PASSES==3: C = Ah*Bh + Ah*Bl + Al*Bh  (2-stage, tiles [Ah|Al|Bh|Bl])
// PASSES==2: C = Ah*Bh + Ah*Bl          (3-stage, tiles [Ah|Bh|Bl])
// PASSES==1: C = Ah*Bh                  (4-stage, tiles [Ah|Bh])
// CTA tile 128x128, BK=32, 8 warps (2x4), warp tile 64x32, fp32 accumulate.
template<int PASSES, bool F16OUT>
__global__ __launch_bounds__(256, 2) void k_hmma(
    const __half* __restrict__ Ah, const __half* __restrict__ Al,
    const __half* __restrict__ A2h, const __half* __restrict__ A2l,
    int lda, int kSplit,
    const __half* __restrict__ Bh, const __half* __restrict__ Bl,
    int ldb, int nBrows,
    float* __restrict__ Cf, __half* __restrict__ Ch, __half* __restrict__ Cl,
    const float* __restrict__ bias,
    int ldc, int M, int Ncols, int nStages,
    size_t sA, size_t sB, size_t sC)
{
    constexpr int TILES = (PASSES == 3) ? 4 : (PASSES == 2) ? 3 : 2;
    constexpr int NST   = (PASSES == 3) ? 2 : (PASSES == 2) ? 3 : 4;
    constexpr int BOFF  = (PASSES == 3) ? 2 : 1;   // Bh tile index
    constexpr uint32_t STGB = (uint32_t)TILES * TSH * 2;

    extern __shared__ __align__(128) __half sm[];
    const int tid = threadIdx.x, lane = tid & 31, wid = tid >> 5;
    const int z = blockIdx.z;
    Ah += sA * z; Al += sA * z; A2h += sA * z; A2l += sA * z;
    Bh += sB * z; Bl += sB * z;
    const size_t cOff = sC * z;
    const int row0 = blockIdx.y * 128;
    const int col0 = blockIdx.x * 128;
    const int warpM = wid >> 2, warpN = wid & 3;

    float acc[4][4][4];
#pragma unroll
    for (int i = 0; i < 4; i++)
#pragma unroll
        for (int j = 0; j < 4; j++)
#pragma unroll
            for (int q = 0; q < 4; q++) acc[i][j][q] = 0.f;

    const uint32_t smb = smem_u32(sm);

    auto fill = [&](int s) {
        int k0 = s * 32;
        const __half *aH, *aL; int koff;
        if (k0 < kSplit) { aH = Ah;  aL = Al;  koff = k0; }
        else             { aH = A2h; aL = A2l; koff = k0 - kSplit; }
        uint32_t base = smb + (uint32_t)(s % NST) * STGB;
#pragma unroll
        for (int l = 0; l < 2; l++) {
            int i = tid + l * 256;
            int r = i >> 2, c = (i & 3) * 8;
            uint32_t d = base + (uint32_t)(r * 40 + c) * 2;
            int okA = (row0 + r < M) ? 16 : 0;
            size_t oA = okA ? ((size_t)(row0 + r) * lda + koff + c) : 0;
            cp16(d, aH + oA, okA);
            if (PASSES == 3) cp16(d + TSH * 2, aL + oA, okA);
            int okB = (col0 + r < nBrows) ? 16 : 0;
            size_t oB = okB ? ((size_t)(col0 + r) * ldb + k0 + c) : 0;
            cp16(d + (uint32_t)BOFF * TSH * 2, Bh + oB, okB);
            if (PASSES >= 2) cp16(d + (uint32_t)(BOFF + 1) * TSH * 2, Bl + oB, okB);
        }
    };

    auto compute = [&](int s) {
        uint32_t base = smb + (uint32_t)(s % NST) * STGB;
        uint32_t bA_h = base;
        uint32_t bA_l = base + TSH * 2;                      // valid only PASSES==3
        uint32_t bB_h = base + (uint32_t)BOFF * TSH * 2;
        uint32_t bB_l = bB_h + TSH * 2;                      // valid only PASSES>=2
#pragma unroll
        for (int kk = 0; kk < 2; kk++) {
            const int k0 = kk * 16;
            uint32_t aoff = (uint32_t)(((warpM * 64 + (lane & 15)) * 40
                             + k0 + ((lane >> 4) << 3)) * 2);
            uint32_t boff = (uint32_t)(((warpN * 32 + ((lane >> 4) << 3) + (lane & 7)) * 40
                             + k0 + ((lane >> 3) & 1) * 8) * 2);
            uint32_t a_h[4][4], b_h[8];
#pragma unroll
            for (int i = 0; i < 4; i++)
                LDSM4(a_h[i][0], a_h[i][1], a_h[i][2], a_h[i][3], bA_h + aoff + i * 1280);
            LDSM4(b_h[0], b_h[1], b_h[2], b_h[3], bB_h + boff);
            LDSM4(b_h[4], b_h[5], b_h[6], b_h[7], bB_h + boff + 1280);
            // pass 1: Ah*Bh
#pragma unroll
            for (int i = 0; i < 4; i++)
#pragma unroll
                for (int j = 0; j < 4; j++)
                    HMMA(acc[i][j], a_h[i], b_h[2*j], b_h[2*j+1]);
            if (PASSES >= 2) {
                uint32_t b_l[8];
                LDSM4(b_l[0], b_l[1], b_l[2], b_l[3], bB_l + boff);
                LDSM4(b_l[4], b_l[5], b_l[6], b_l[7], bB_l + boff + 1280);
#pragma unroll
                for (int i = 0; i < 4; i++)
#pragma unroll
                    for (int j = 0; j < 4; j++)
                        HMMA(acc[i][j], a_h[i], b_l[2*j], b_l[2*j+1]);
            }
            if (PASSES == 3) {
                uint32_t a_l[4][4];
#pragma unroll
                for (int i = 0; i < 4; i++)
                    LDSM4(a_l[i][0], a_l[i][1], a_l[i][2], a_l[i][3], bA_l + aoff + i * 1280);
#pragma unroll
                for (int i = 0; i < 4; i++)
#pragma unroll
                    for (int j = 0; j < 4; j++)
                        HMMA(acc[i][j], a_l[i], b_h[2*j], b_h[2*j+1]);
            }
        }
    };

    // generic NST-deep pipeline, one __syncthreads per stage
#pragma unroll 1
    for (int i = 0; i < NST - 1 && i < nStages; i++) { fill(i); CP_COMMIT(); }
#pragma unroll 1
    for (int s = 0; s < nStages; s++) {
        if (nStages - s > NST - 1) { CP_WAIT(NST - 2); }
        else                       { CP_WAIT(0); }
        __syncthreads();
        if (s + NST - 1 < nStages) { fill(s + NST - 1); CP_COMMIT(); }
        compute(s);
    }

    // epilogue: registers -> global
#pragma unroll
    for (int i = 0; i < 4; i++) {
        int gm0 = row0 + warpM * 64 + i * 16 + (lane >> 2);
#pragma unroll
        for (int j = 0; j < 4; j++) {
            int gn = col0 + warpN * 32 + j * 8 + 2 * (lane & 3);
            float b0 = 0.f, b1 = 0.f;
            if (bias) {
                if (gn     < Ncols) b0 = bias[gn];
                if (gn + 1 < Ncols) b1 = bias[gn + 1];
            }
#pragma unroll
            for (int h = 0; h < 2; h++) {
                int gm = gm0 + h * 8;
                if (gm >= M) continue;
                float c0 = acc[i][j][2*h]     + b0;
                float c1 = acc[i][j][2*h + 1] + b1;
                if (F16OUT) {
                    size_t o = cOff + (size_t)gm * ldc + gn;
                    if (gn < Ncols) { __half hh, ll; split16(c0, hh, ll); Ch[o] = hh; Cl[o] = ll; }
                    if (gn + 1 < Ncols) { __half hh, ll; split16(c1, hh, ll); Ch[o+1] = hh; Cl[o+1] = ll; }
                } else {
                    float* dst = Cf + cOff + (size_t)gm * ldc + gn;
                    if (gn     < Ncols) dst[0] = c0;
                    if (gn + 1 < Ncols) dst[1] = c1;
                }
            }
        }
    }
}

// ================= fused preprocessing (ONE launch) =================
#define PREP_NB 8486
__global__ void k_prep(const float* __restrict__ x,
                       const float* __restrict__ conv_w,
                       const float* __restrict__ attn_w,
                       const float* __restrict__ cls_w,
                       const float* __restrict__ reg_w,
                       const float* __restrict__ cls_b,
                       const float* __restrict__ reg_b,
                       const unsigned int* __restrict__ invw) {
    int bid = blockIdx.x;
    int tid = threadIdx.x;
    if (bid < 1024) {
        __shared__ float tile[32][33];
        int b  = bid >> 7;
        int rem = bid & 127;
        int p0 = (rem & 7) * 32;
        int c0 = (rem >> 3) * 32;
        int tx = tid & 31, ty = tid >> 5;
        for (int i = ty; i < 32; i += 8) {
            int c = c0 + i, p = p0 + tx;
            float v = 0.f;
            if (p < HW) v = x[((size_t)b*CIN + c)*HW + p];
            tile[i][tx] = v;
        }
        __syncthreads();
        for (int i = ty; i < 32; i += 8) {
            int p = p0 + i, c = c0 + tx;
            if (p < HW) {
                float v = tile[tx][i];
                __half h, l; split16(v, h, l);
                size_t o = ((size_t)b*HW + p)*CIN + c;
                g_xh[o] = h; g_xl[o] = l;
            }
        }
    } else if (bid < 1152) {
        int i = (bid - 1024) * 256 + tid;
        if (i < CF*CIN) { __half h, l; split16(conv_w[i], h, l); g_cwh[i] = h; g_cwl[i] = l; }
    } else if (bid < 8110) {
        int i = (bid - 1152) * 256 + tid;
        if (i < MCOL*DF) g_awh[i] = __float2half_rn(attn_w[i]);
    } else if (bid < 8485) {
        int i = (bid - 8110) * 256 + tid;
        if (i < 75*KCAT) {
            float v = (i < 2*KCAT) ? cls_w[i] : reg_w[i - 2*KCAT];
            __half h, l; split16(v, h, l);
            g_wh[i] = h; g_wl[i] = l;
        }
    } else {
        __shared__ int s_float, s_byte;
        if (tid == 0) { s_float = 0; s_byte = 0; }
        __syncthreads();
        for (int i = tid; i < NINV/4; i += 256) {
            unsigned int v = invw[i];
            if (v == 0x3F800000u) atomicOr(&s_float, 1);
            else if (v & 0xFFFFFF00u) atomicOr(&s_byte, 1);
        }
        __syncthreads();
        int wordmode = (s_float || !s_byte) ? 1 : 0;
        const unsigned char* invb = (const unsigned char*)invw;
        for (int i = tid; i < NINV; i += 256)
            g_inv[i] = wordmode ? (invw[i] ? 1 : 0) : (invb[i] ? 1 : 0);
        if (tid < 2) g_b75[tid] = cls_b[tid];
        else if (tid < 75) g_b75[tid] = reg_b[tid - 2];
    }
}

// gather
__global__ void k_gather16(const int* __restrict__ cut_xs) {
    size_t idx = (size_t)blockIdx.x * 256 + threadIdx.x;
    const size_t total = (size_t)BATCH*NANCH*DF;
    if (idx >= total) return;
    int d = (int)(idx % DF);
    size_t r = idx / DF;
    int n = (int)(r % NANCH);
    int b = (int)(r / NANCH);
    int c = d / HF, h = d % HF;
    int xs = cut_xs[n*HF + h];
    float v = 0.f;
    if (!g_inv[n*HF + h])
        v = g_feat[(((size_t)b*HF + h)*WF + xs)*CF + c];
    __half hh, ll; split16(v, hh, ll);
    g_pfh[idx] = hh; g_pfl[idx] = ll;
}

// pf16 transpose (hi only — attgemm B operand)
__global__ void k_pfT16() {
    __shared__ __half tile[32][33];
    int b = blockIdx.z;
    const __half* src = g_pfh + (size_t)b*NANCH*DF;
    __half*       dst = g_pth + (size_t)b*DF*NANCH;
    int n0 = blockIdx.x * 32;
    int d0 = blockIdx.y * 32;
    for (int i = threadIdx.y; i < 32; i += 8)
        tile[i][threadIdx.x] = src[(size_t)(n0 + i)*DF + d0 + threadIdx.x];
    __syncthreads();
    for (int i = threadIdx.y; i < 32; i += 8)
        dst[(size_t)(d0 + i)*NANCH + n0 + threadIdx.x] = tile[threadIdx.x][i];
}

// softmax: writes f32 attn output and f16 (hi only) probs
__global__ __launch_bounds__(256) void k_softmax(float* __restrict__ attn_out) {
    int row = blockIdx.x;
    int i = row % NANCH;
    const float* s = g_sc + (size_t)row * LDSC;
    __shared__ float buf[MCOL];
    __shared__ float red[8];
    int tid = threadIdx.x;

    float mx = -1e30f;
    for (int m = tid; m < MCOL; m += 256) { float v = s[m]; buf[m] = v; mx = fmaxf(mx, v); }
#pragma unroll
    for (int o = 16; o > 0; o >>= 1) mx = fmaxf(mx, __shfl_xor_sync(0xffffffffu, mx, o));
    if ((tid & 31) == 0) red[tid >> 5] = mx;
    __syncthreads();
    float mall = red[0];
#pragma unroll
    for (int w = 1; w < 8; w++) mall = fmaxf(mall, red[w]);

    float sum = 0.f;
    for (int m = tid; m < MCOL; m += 256) { float e = __expf(buf[m] - mall); buf[m] = e; sum += e; }
#pragma unroll
    for (int o = 16; o > 0; o >>= 1) sum += __shfl_xor_sync(0xffffffffu, sum, o);
    __syncthreads();
    if ((tid & 31) == 0) red[tid >> 5] = sum;
    __syncthreads();
    float total = 0.f;
#pragma unroll
    for (int w = 0; w < 8; w++) total += red[w];
    float inv = 1.f / total;

    float* out = attn_out + (size_t)row * NANCH;
    __half* oh = g_prh + (size_t)row * NANCH;
    for (int m = tid; m < MCOL; m += 256) {
        int j = m + (m >= i);
        float v = buf[m] * inv;
        out[j] = v;
        oh[j] = __float2half_rn(v);
    }
    if (tid == 0) { out[i] = 0.f; oh[i] = __float2half(0.f); }
}

// finalize
__global__ void k_finalize(const float* __restrict__ anchors,
                           float* __restrict__ out_cls, float* __restrict__ out_lanes) {
    size_t idx = (size_t)blockIdx.x * 256 + threadIdx.x;
    const size_t total = (size_t)MROWS * 79;
    if (idx >= total) return;
    int c = (int)(idx % 79);
    int gr = (int)(idx / 79);
    int n = gr % NANCH;
    if (c < 2) {
        out_cls[(size_t)gr*2 + c] = g_head[(size_t)gr*75 + c];
    } else {
        int lc = c - 2;
        float v;
        if (lc < 4)       v = anchors[(size_t)n*77 + lc];
        else if (lc == 4) v = g_head[(size_t)gr*75 + 2];
        else              v = anchors[(size_t)n*77 + lc] + g_head[(size_t)gr*75 + lc - 2];
        out_lanes[(size_t)gr*77 + lc] = v;
    }
}

// ---------------- launch ----------------
extern "C" void kernel_launch(void* const* d_in, const int* in_sizes, int n_in,
                              void* d_out, int out_size) {
    const void* ptr[12];
    for (int i = 0; i < 12 && i < n_in; i++) ptr[i] = d_in[i];
    {
        int seen27840 = 0;
        for (int i = 0; i < n_in; i++) {
            switch (in_sizes[i]) {
                case 1024000: ptr[0]  = d_in[i]; break; // x
                case 32768:   ptr[1]  = d_in[i]; break; // conv_w
                case 64:      ptr[2]  = d_in[i]; break; // conv_b
                case 1781120: ptr[3]  = d_in[i]; break; // attn_w
                case 2783:    ptr[4]  = d_in[i]; break; // attn_b
                case 2560:    ptr[5]  = d_in[i]; break; // cls_w
                case 2:       ptr[6]  = d_in[i]; break; // cls_b
                case 93440:   ptr[7]  = d_in[i]; break; // reg_w
                case 73:      ptr[8]  = d_in[i]; break; // reg_b
                case 214368:  ptr[9]  = d_in[i]; break; // anchors
                case 27840:
                    if (seen27840 == 0) ptr[10] = d_in[i];
                    else                ptr[11] = d_in[i];
                    seen27840++;
                    break;
                default: break;
            }
        }
    }
    const float* x        = (const float*)ptr[0];
    const float* conv_w   = (const float*)ptr[1];
    const float* conv_b   = (const float*)ptr[2];
    const float* attn_w   = (const float*)ptr[3];
    const float* attn_b   = (const float*)ptr[4];
    const float* cls_w    = (const float*)ptr[5];
    const float* cls_b    = (const float*)ptr[6];
    const float* reg_w    = (const float*)ptr[7];
    const float* reg_b    = (const float*)ptr[8];
    const float* anchors  = (const float*)ptr[9];
    const int*   cut_xs   = (const int*)ptr[10];
    const void*  invalid  = ptr[11];

    float* out      = (float*)d_out;
    float* o_cls    = out;
    float* o_lanes  = out + (size_t)MROWS*2;
    float* o_attn   = out + (size_t)MROWS*79;

    __half *xh,*xl,*cwh,*cwl,*awh,*pfh,*pfl,*pth,*prh,*afh,*afl,*wh,*wl;
    float *b75,*head,*feat,*sc;
    cudaGetSymbolAddress((void**)&xh, g_xh);   cudaGetSymbolAddress((void**)&xl, g_xl);
    cudaGetSymbolAddress((void**)&cwh, g_cwh); cudaGetSymbolAddress((void**)&cwl, g_cwl);
    cudaGetSymbolAddress((void**)&awh, g_awh);
    cudaGetSymbolAddress((void**)&pfh, g_pfh); cudaGetSymbolAddress((void**)&pfl, g_pfl);
    cudaGetSymbolAddress((void**)&pth, g_pth);
    cudaGetSymbolAddress((void**)&prh, g_prh);
    cudaGetSymbolAddress((void**)&afh, g_afh); cudaGetSymbolAddress((void**)&afl, g_afl);
    cudaGetSymbolAddress((void**)&wh, g_wh);   cudaGetSymbolAddress((void**)&wl, g_wl);
    cudaGetSymbolAddress((void**)&b75, g_b75); cudaGetSymbolAddress((void**)&head, g_head);
    cudaGetSymbolAddress((void**)&feat, g_feat); cudaGetSymbolAddress((void**)&sc, g_sc);

    const int SMEM3 = 2 * 4 * TSH * 2;   // 81920  (3-pass, 2-stage)
    const int SMEM1 = 4 * 2 * TSH * 2;   // 81920  (1-pass, 4-stage)
    cudaFuncSetAttribute(k_hmma<3,false>, cudaFuncAttributeMaxDynamicSharedMemorySize, SMEM3);
    cudaFuncSetAttribute(k_hmma<1,false>, cudaFuncAttributeMaxDynamicSharedMemorySize, SMEM1);
    cudaFuncSetAttribute(k_hmma<1,true>,  cudaFuncAttributeMaxDynamicSharedMemorySize, SMEM1);

    // launch 0: fused prep
    k_prep<<<PREP_NB, 256>>>(x, conv_w, attn_w, cls_w, reg_w, cls_b, reg_b,
                             (const unsigned int*)invalid);

    // launch 1: conv (3-pass; pf accuracy feeds cls directly)
    k_hmma<3,false><<<dim3(1, 16, 1), 256, SMEM3>>>(
        xh, xl, xh, xl, CIN, 1 << 28,
        cwh, cwl, CIN, CF,
        feat, nullptr, nullptr, conv_b,
        CF, BATCH*HW, CF, CIN/32, 0, 0, 0);

    // launch 2: gather
    {
        size_t total = (size_t)BATCH*NANCH*DF;
        k_gather16<<<(unsigned)((total + 255)/256), 256>>>(cut_xs);
    }

    // launch 3 (ncu-captured): scores — flattened M=22272, SINGLE-pass fp16
    // (softmax normalizes the ~3e-5 abs score error)
    k_hmma<1,false><<<dim3(22, MROWS/128, 1), 256, SMEM1>>>(
        pfh, pfh, pfh, pfh, DF, 1 << 28,
        awh, awh, DF, MCOL,
        sc, nullptr, nullptr, attn_b,
        LDSC, MROWS, MCOL, DF/32, 0, 0, 0);

    // launch 4: softmax
    k_softmax<<<BATCH*NANCH, 256>>>(o_attn);

    // launch 5: pf transpose (hi only)
    k_pfT16<<<dim3(NANCH/32, DF/32, BATCH), dim3(32, 8)>>>();

    // launch 6: att_feats — SINGLE-pass fp16 (att errors diluted by pf in cat)
    k_hmma<1,true><<<dim3(5, 22, BATCH), 256, SMEM1>>>(
        prh, prh, prh, prh, NANCH, 1 << 28,
        pth, pth, NANCH, DF,
        nullptr, afh, afl, nullptr,
        DF, NANCH, DF, NANCH/32,
        (size_t)NANCH*NANCH, (size_t)DF*NANCH, (size_t)NANCH*DF);

    // launch 7: head (3-pass, exact path for cls/reg)
    k_hmma<3,false><<<dim3(1, MROWS/128, 1), 256, SMEM3>>>(
        afh, afl, pfh, pfl, DF, DF,
        wh, wl, KCAT, 75,
        head, nullptr, nullptr, b75,
        75, MROWS, 75, KCAT/32, 0, 0, 0);

    // launch 8: finalize
    {
        size_t total = (size_t)MROWS * 79;
        k_finalize<<<(unsigned)((total + 255)/256), 256>>>(anchors, o_cls, o_lanes);
    }
}

// round 11
// speedup vs baseline: 1.8761x; 1.0653x over previous
#include <cuda_runtime.h>
#include <cuda_fp16.h>
#include <cstdint>

// ---------------- problem constants ----------------
#define BATCH 8
#define CIN   512
#define HF    10
#define WF    25
#define HW    250          // HF*WF
#define CF    64
#define NANCH 2784         // total anchors N
#define MCOL  2783         // N-1
#define DF    640          // CF*HF
#define LDSC  2784         // padded scores row stride
#define KCAT  1280         // 2*DF
#define NINV  (NANCH*HF)   // 27840 mask entries
#define MROWS (BATCH*NANCH) // 22272
#define TSH   5120         // halves per smem tile (128 rows * 40 padded)

// ---------------- scratch (device globals; no allocation allowed) ----------------
__device__ __align__(128) __half g_xh [(size_t)BATCH*HW*CIN];
__device__ __align__(128) __half g_xl [(size_t)BATCH*HW*CIN];
__device__ __align__(128) __half g_cwh[(size_t)CF*CIN];
__device__ __align__(128) __half g_cwl[(size_t)CF*CIN];
__device__ __align__(128) __half g_awh[(size_t)MCOL*DF];
__device__ __align__(128) __half g_pfh[(size_t)BATCH*NANCH*DF];
__device__ __align__(128) __half g_pfl[(size_t)BATCH*NANCH*DF];
__device__ __align__(128) __half g_pth[(size_t)BATCH*DF*NANCH];
__device__ __align__(128) __half g_prh[(size_t)BATCH*NANCH*NANCH];  // softmax probs hi
__device__ __align__(128) __half g_afh[(size_t)BATCH*NANCH*DF];
__device__ __align__(128) __half g_afl[(size_t)BATCH*NANCH*DF];
__device__ __align__(128) __half g_wh [(size_t)75*KCAT];
__device__ __align__(128) __half g_wl [(size_t)75*KCAT];
__device__ __align__(128) float  g_b75[80];
__device__ __align__(128) float  g_head[(size_t)MROWS*75];
__device__ __align__(128) float  g_feat[(size_t)BATCH*HW*CF];
__device__ __align__(128) __half g_sc  [(size_t)MROWS*LDSC];        // scores (f16)
__device__ unsigned char g_inv[NINV];

// ---------------- helpers ----------------
__device__ __forceinline__ uint32_t smem_u32(const void* p) {
    uint32_t a;
    asm("{ .reg .u64 t; cvta.to.shared.u64 t, %1; cvt.u32.u64 %0, t; }" : "=r"(a) : "l"(p));
    return a;
}
__device__ __forceinline__ void cp16(uint32_t dst, const void* src, int sz) {
    asm volatile("cp.async.ca.shared.global [%0], [%1], 16, %2;" :: "r"(dst), "l"(src), "r"(sz) : "memory");
}
#define CP_COMMIT() asm volatile("cp.async.commit_group;" ::: "memory")
#define CP_WAIT(n)  asm volatile("cp.async.wait_group %0;" :: "n"(n) : "memory")
#define LDSM4(R0,R1,R2,R3,ADDR) \
    asm volatile("ldmatrix.sync.aligned.m8n8.x4.shared.b16 {%0,%1,%2,%3}, [%4];" \
        : "=r"(R0), "=r"(R1), "=r"(R2), "=r"(R3) : "r"(ADDR))
#define HMMA(C,A,B0,B1) \
    asm volatile("mma.sync.aligned.m16n8k16.row.col.f32.f16.f16.f32 " \
        "{%0,%1,%2,%3}, {%4,%5,%6,%7}, {%8,%9}, {%0,%1,%2,%3};" \
        : "+f"((C)[0]), "+f"((C)[1]), "+f"((C)[2]), "+f"((C)[3]) \
        : "r"((A)[0]), "r"((A)[1]), "r"((A)[2]), "r"((A)[3]), "r"(B0), "r"(B1))

__device__ __forceinline__ void split16(float v, __half& h, __half& l) {
    h = __float2half_rn(v);
    l = __float2half_rn(v - __half2float(h));
}

// ================= single-pass fp16 GEMM, big warp tiles =================
// C[m,n] = sum_k Ah[m,k]*Bh[n,k] (NT), fp32 accumulate.
// 128 threads, 4 warps (2x2), warp tile 64x64, CTA 128x128, BK=32, 4-stage.
// OUTM: 0 = f32, 1 = f16 hi/lo pair, 2 = f16 single.
template<int OUTM>
__global__ __launch_bounds__(128, 2) void k_big(
    const __half* __restrict__ Ah, int lda,
    const __half* __restrict__ Bh, int ldb, int nBrows,
    float* __restrict__ Cf, __half* __restrict__ Ch, __half* __restrict__ Cl,
    const float* __restrict__ bias,
    int ldc, int M, int Ncols, int nStages,
    size_t sA, size_t sB, size_t sC)
{
    constexpr int NST = 4;
    constexpr uint32_t STGB = 2u * TSH * 2;   // A+B tiles = 20480 B/stage

    extern __shared__ __align__(128) __half sm[];
    const int tid = threadIdx.x, lane = tid & 31, wid = tid >> 5;
    const int z = blockIdx.z;
    Ah += sA * z; Bh += sB * z;
    const size_t cOff = sC * z;
    const int row0 = blockIdx.y * 128;
    const int col0 = blockIdx.x * 128;
    const int warpM = wid & 1, warpN = wid >> 1;

    float acc[4][8][4];
#pragma unroll
    for (int i = 0; i < 4; i++)
#pragma unroll
        for (int j = 0; j < 8; j++)
#pragma unroll
            for (int q = 0; q < 4; q++) acc[i][j][q] = 0.f;

    const uint32_t smb = smem_u32(sm);

    auto fill = [&](int s) {
        int k0 = s * 32;
        uint32_t base = smb + (uint32_t)(s % NST) * STGB;
#pragma unroll
        for (int l = 0; l < 8; l++) {
            int i = tid + l * 128;          // 0..1023
            int t = i >> 9;                 // 0 = A tile, 1 = B tile
            int r = (i >> 2) & 127;
            int c = (i & 3) * 8;
            uint32_t d = base + (uint32_t)t * (TSH * 2) + (uint32_t)(r * 40 + c) * 2;
            if (t == 0) {
                int ok = (row0 + r < M) ? 16 : 0;
                size_t o = ok ? ((size_t)(row0 + r) * lda + k0 + c) : 0;
                cp16(d, Ah + o, ok);
            } else {
                int ok = (col0 + r < nBrows) ? 16 : 0;
                size_t o = ok ? ((size_t)(col0 + r) * ldb + k0 + c) : 0;
                cp16(d, Bh + o, ok);
            }
        }
    };

    auto compute = [&](int s) {
        uint32_t base = smb + (uint32_t)(s % NST) * STGB;
        uint32_t bA = base, bB = base + TSH * 2;
#pragma unroll
        for (int kk = 0; kk < 2; kk++) {
            const int k0 = kk * 16;
            uint32_t aoff = (uint32_t)(((warpM * 64 + (lane & 15)) * 40
                             + k0 + ((lane >> 4) << 3)) * 2);
            uint32_t boff = (uint32_t)(((warpN * 64 + ((lane >> 4) << 3) + (lane & 7)) * 40
                             + k0 + ((lane >> 3) & 1) * 8) * 2);
            uint32_t a[4][4], b[16];
#pragma unroll
            for (int i = 0; i < 4; i++)
                LDSM4(a[i][0], a[i][1], a[i][2], a[i][3], bA + aoff + i * 1280);
#pragma unroll
            for (int nb = 0; nb < 4; nb++)
                LDSM4(b[nb*4+0], b[nb*4+1], b[nb*4+2], b[nb*4+3], bB + boff + nb * 1280);
#pragma unroll
            for (int i = 0; i < 4; i++)
#pragma unroll
                for (int j = 0; j < 8; j++)
                    HMMA(acc[i][j], a[i], b[2*j], b[2*j+1]);
        }
    };

#pragma unroll 1
    for (int i = 0; i < NST - 1 && i < nStages; i++) { fill(i); CP_COMMIT(); }
#pragma unroll 1
    for (int s = 0; s < nStages; s++) {
        if (nStages - s > NST - 1) { CP_WAIT(NST - 2); }
        else                       { CP_WAIT(0); }
        __syncthreads();
        if (s + NST - 1 < nStages) { fill(s + NST - 1); CP_COMMIT(); }
        compute(s);
    }

    // epilogue
#pragma unroll
    for (int i = 0; i < 4; i++) {
        int gm0 = row0 + warpM * 64 + i * 16 + (lane >> 2);
#pragma unroll
        for (int j = 0; j < 8; j++) {
            int gn = col0 + warpN * 64 + j * 8 + 2 * (lane & 3);
            float b0 = 0.f, b1 = 0.f;
            if (bias) {
                if (gn     < Ncols) b0 = bias[gn];
                if (gn + 1 < Ncols) b1 = bias[gn + 1];
            }
#pragma unroll
            for (int h = 0; h < 2; h++) {
                int gm = gm0 + h * 8;
                if (gm >= M) continue;
                float c0 = acc[i][j][2*h]     + b0;
                float c1 = acc[i][j][2*h + 1] + b1;
                size_t o = cOff + (size_t)gm * ldc + gn;
                if (OUTM == 0) {
                    if (gn     < Ncols) Cf[o]   = c0;
                    if (gn + 1 < Ncols) Cf[o+1] = c1;
                } else if (OUTM == 1) {
                    if (gn < Ncols) { __half hh, ll; split16(c0, hh, ll); Ch[o] = hh; Cl[o] = ll; }
                    if (gn + 1 < Ncols) { __half hh, ll; split16(c1, hh, ll); Ch[o+1] = hh; Cl[o+1] = ll; }
                } else {
                    if (gn     < Ncols) Ch[o]   = __float2half_rn(c0);
                    if (gn + 1 < Ncols) Ch[o+1] = __float2half_rn(c1);
                }
            }
        }
    }
}

// ================= fp16 split 3-pass HMMA GEMM (exact path: conv, head) =====
template<bool DUMMY>
__global__ __launch_bounds__(256, 2) void k_hmma3(
    const __half* __restrict__ Ah, const __half* __restrict__ Al,
    const __half* __restrict__ A2h, const __half* __restrict__ A2l,
    int lda, int kSplit,
    const __half* __restrict__ Bh, const __half* __restrict__ Bl,
    int ldb, int nBrows,
    float* __restrict__ Cf, const float* __restrict__ bias,
    int ldc, int M, int Ncols, int nStages)
{
    constexpr uint32_t STGB = 4u * TSH * 2;
    extern __shared__ __align__(128) __half sm[];
    const int tid = threadIdx.x, lane = tid & 31, wid = tid >> 5;
    const int row0 = blockIdx.y * 128;
    const int col0 = blockIdx.x * 128;
    const int warpM = wid >> 2, warpN = wid & 3;

    float acc[4][4][4];
#pragma unroll
    for (int i = 0; i < 4; i++)
#pragma unroll
        for (int j = 0; j < 4; j++)
#pragma unroll
            for (int q = 0; q < 4; q++) acc[i][j][q] = 0.f;

    const uint32_t smb = smem_u32(sm);

    auto fill = [&](int s) {
        int k0 = s * 32;
        const __half *aH, *aL; int koff;
        if (k0 < kSplit) { aH = Ah;  aL = Al;  koff = k0; }
        else             { aH = A2h; aL = A2l; koff = k0 - kSplit; }
        uint32_t base = smb + (uint32_t)(s & 1) * STGB;
#pragma unroll
        for (int l = 0; l < 2; l++) {
            int i = tid + l * 256;
            int r = i >> 2, c = (i & 3) * 8;
            uint32_t d = base + (uint32_t)(r * 40 + c) * 2;
            int okA = (row0 + r < M) ? 16 : 0;
            size_t oA = okA ? ((size_t)(row0 + r) * lda + koff + c) : 0;
            cp16(d,           aH + oA, okA);
            cp16(d + TSH * 2, aL + oA, okA);
            int okB = (col0 + r < nBrows) ? 16 : 0;
            size_t oB = okB ? ((size_t)(col0 + r) * ldb + k0 + c) : 0;
            cp16(d + 2 * TSH * 2, Bh + oB, okB);
            cp16(d + 3 * TSH * 2, Bl + oB, okB);
        }
    };

    fill(0); CP_COMMIT();
    for (int s = 0; s < nStages; s++) {
        if (s + 1 < nStages) { fill(s + 1); CP_COMMIT(); CP_WAIT(1); }
        else                 { CP_WAIT(0); }
        __syncthreads();
        uint32_t bA_h = smb + (uint32_t)(s & 1) * STGB;
        uint32_t bA_l = bA_h + TSH * 2;
        uint32_t bB_h = bA_h + 2 * TSH * 2;
        uint32_t bB_l = bA_h + 3 * TSH * 2;
#pragma unroll
        for (int kk = 0; kk < 2; kk++) {
            const int k0 = kk * 16;
            uint32_t aoff = (uint32_t)(((warpM * 64 + (lane & 15)) * 40
                             + k0 + ((lane >> 4) << 3)) * 2);
            uint32_t boff = (uint32_t)(((warpN * 32 + ((lane >> 4) << 3) + (lane & 7)) * 40
                             + k0 + ((lane >> 3) & 1) * 8) * 2);
            uint32_t a_h[4][4], b_h[8];
#pragma unroll
            for (int i = 0; i < 4; i++)
                LDSM4(a_h[i][0], a_h[i][1], a_h[i][2], a_h[i][3], bA_h + aoff + i * 1280);
            LDSM4(b_h[0], b_h[1], b_h[2], b_h[3], bB_h + boff);
            LDSM4(b_h[4], b_h[5], b_h[6], b_h[7], bB_h + boff + 1280);
#pragma unroll
            for (int i = 0; i < 4; i++)
#pragma unroll
                for (int j = 0; j < 4; j++)
                    HMMA(acc[i][j], a_h[i], b_h[2*j], b_h[2*j+1]);
            uint32_t b_l[8];
            LDSM4(b_l[0], b_l[1], b_l[2], b_l[3], bB_l + boff);
            LDSM4(b_l[4], b_l[5], b_l[6], b_l[7], bB_l + boff + 1280);
#pragma unroll
            for (int i = 0; i < 4; i++)
#pragma unroll
                for (int j = 0; j < 4; j++)
                    HMMA(acc[i][j], a_h[i], b_l[2*j], b_l[2*j+1]);
            uint32_t a_l[4][4];
#pragma unroll
            for (int i = 0; i < 4; i++)
                LDSM4(a_l[i][0], a_l[i][1], a_l[i][2], a_l[i][3], bA_l + aoff + i * 1280);
#pragma unroll
            for (int i = 0; i < 4; i++)
#pragma unroll
                for (int j = 0; j < 4; j++)
                    HMMA(acc[i][j], a_l[i], b_h[2*j], b_h[2*j+1]);
        }
        __syncthreads();
    }

#pragma unroll
    for (int i = 0; i < 4; i++) {
        int gm0 = row0 + warpM * 64 + i * 16 + (lane >> 2);
#pragma unroll
        for (int j = 0; j < 4; j++) {
            int gn = col0 + warpN * 32 + j * 8 + 2 * (lane & 3);
            float b0 = 0.f, b1 = 0.f;
            if (bias) {
                if (gn     < Ncols) b0 = bias[gn];
                if (gn + 1 < Ncols) b1 = bias[gn + 1];
            }
#pragma unroll
            for (int h = 0; h < 2; h++) {
                int gm = gm0 + h * 8;
                if (gm >= M) continue;
                float* dst = Cf + (size_t)gm * ldc + gn;
                if (gn     < Ncols) dst[0] = acc[i][j][2*h]     + b0;
                if (gn + 1 < Ncols) dst[1] = acc[i][j][2*h + 1] + b1;
            }
        }
    }
}

// ================= fused preprocessing (ONE launch) =================
#define PREP_NB 8486
__global__ void k_prep(const float* __restrict__ x,
                       const float* __restrict__ conv_w,
                       const float* __restrict__ attn_w,
                       const float* __restrict__ cls_w,
                       const float* __restrict__ reg_w,
                       const float* __restrict__ cls_b,
                       const float* __restrict__ reg_b,
                       const unsigned int* __restrict__ invw) {
    int bid = blockIdx.x;
    int tid = threadIdx.x;
    if (bid < 1024) {
        __shared__ float tile[32][33];
        int b  = bid >> 7;
        int rem = bid & 127;
        int p0 = (rem & 7) * 32;
        int c0 = (rem >> 3) * 32;
        int tx = tid & 31, ty = tid >> 5;
        for (int i = ty; i < 32; i += 8) {
            int c = c0 + i, p = p0 + tx;
            float v = 0.f;
            if (p < HW) v = x[((size_t)b*CIN + c)*HW + p];
            tile[i][tx] = v;
        }
        __syncthreads();
        for (int i = ty; i < 32; i += 8) {
            int p = p0 + i, c = c0 + tx;
            if (p < HW) {
                float v = tile[tx][i];
                __half h, l; split16(v, h, l);
                size_t o = ((size_t)b*HW + p)*CIN + c;
                g_xh[o] = h; g_xl[o] = l;
            }
        }
    } else if (bid < 1152) {
        int i = (bid - 1024) * 256 + tid;
        if (i < CF*CIN) { __half h, l; split16(conv_w[i], h, l); g_cwh[i] = h; g_cwl[i] = l; }
    } else if (bid < 8110) {
        int i = (bid - 1152) * 256 + tid;
        if (i < MCOL*DF) g_awh[i] = __float2half_rn(attn_w[i]);
    } else if (bid < 8485) {
        int i = (bid - 8110) * 256 + tid;
        if (i < 75*KCAT) {
            float v = (i < 2*KCAT) ? cls_w[i] : reg_w[i - 2*KCAT];
            __half h, l; split16(v, h, l);
            g_wh[i] = h; g_wl[i] = l;
        }
    } else {
        __shared__ int s_float, s_byte;
        if (tid == 0) { s_float = 0; s_byte = 0; }
        __syncthreads();
        for (int i = tid; i < NINV/4; i += 256) {
            unsigned int v = invw[i];
            if (v == 0x3F800000u) atomicOr(&s_float, 1);
            else if (v & 0xFFFFFF00u) atomicOr(&s_byte, 1);
        }
        __syncthreads();
        int wordmode = (s_float || !s_byte) ? 1 : 0;
        const unsigned char* invb = (const unsigned char*)invw;
        for (int i = tid; i < NINV; i += 256)
            g_inv[i] = wordmode ? (invw[i] ? 1 : 0) : (invb[i] ? 1 : 0);
        if (tid < 2) g_b75[tid] = cls_b[tid];
        else if (tid < 75) g_b75[tid] = reg_b[tid - 2];
    }
}

// gather
__global__ void k_gather16(const int* __restrict__ cut_xs) {
    size_t idx = (size_t)blockIdx.x * 256 + threadIdx.x;
    const size_t total = (size_t)BATCH*NANCH*DF;
    if (idx >= total) return;
    int d = (int)(idx % DF);
    size_t r = idx / DF;
    int n = (int)(r % NANCH);
    int b = (int)(r / NANCH);
    int c = d / HF, h = d % HF;
    int xs = cut_xs[n*HF + h];
    float v = 0.f;
    if (!g_inv[n*HF + h])
        v = g_feat[(((size_t)b*HF + h)*WF + xs)*CF + c];
    __half hh, ll; split16(v, hh, ll);
    g_pfh[idx] = hh; g_pfl[idx] = ll;
}

// pf16 transpose (hi only — attgemm B operand)
__global__ void k_pfT16() {
    __shared__ __half tile[32][33];
    int b = blockIdx.z;
    const __half* src = g_pfh + (size_t)b*NANCH*DF;
    __half*       dst = g_pth + (size_t)b*DF*NANCH;
    int n0 = blockIdx.x * 32;
    int d0 = blockIdx.y * 32;
    for (int i = threadIdx.y; i < 32; i += 8)
        tile[i][threadIdx.x] = src[(size_t)(n0 + i)*DF + d0 + threadIdx.x];
    __syncthreads();
    for (int i = threadIdx.y; i < 32; i += 8)
        dst[(size_t)(d0 + i)*NANCH + n0 + threadIdx.x] = tile[threadIdx.x][i];
}

// softmax: reads f16 scores, writes f32 attn output and f16 probs
__global__ __launch_bounds__(256) void k_softmax(float* __restrict__ attn_out) {
    int row = blockIdx.x;
    int i = row % NANCH;
    const __half* s = g_sc + (size_t)row * LDSC;
    __shared__ float buf[MCOL];
    __shared__ float red[8];
    int tid = threadIdx.x;

    float mx = -1e30f;
    for (int m = tid; m < MCOL; m += 256) { float v = __half2float(s[m]); buf[m] = v; mx = fmaxf(mx, v); }
#pragma unroll
    for (int o = 16; o > 0; o >>= 1) mx = fmaxf(mx, __shfl_xor_sync(0xffffffffu, mx, o));
    if ((tid & 31) == 0) red[tid >> 5] = mx;
    __syncthreads();
    float mall = red[0];
#pragma unroll
    for (int w = 1; w < 8; w++) mall = fmaxf(mall, red[w]);

    float sum = 0.f;
    for (int m = tid; m < MCOL; m += 256) { float e = __expf(buf[m] - mall); buf[m] = e; sum += e; }
#pragma unroll
    for (int o = 16; o > 0; o >>= 1) sum += __shfl_xor_sync(0xffffffffu, sum, o);
    __syncthreads();
    if ((tid & 31) == 0) red[tid >> 5] = sum;
    __syncthreads();
    float total = 0.f;
#pragma unroll
    for (int w = 0; w < 8; w++) total += red[w];
    float inv = 1.f / total;

    float* out = attn_out + (size_t)row * NANCH;
    __half* oh = g_prh + (size_t)row * NANCH;
    for (int m = tid; m < MCOL; m += 256) {
        int j = m + (m >= i);
        float v = buf[m] * inv;
        out[j] = v;
        oh[j] = __float2half_rn(v);
    }
    if (tid == 0) { out[i] = 0.f; oh[i] = __float2half(0.f); }
}

// finalize
__global__ void k_finalize(const float* __restrict__ anchors,
                           float* __restrict__ out_cls, float* __restrict__ out_lanes) {
    size_t idx = (size_t)blockIdx.x * 256 + threadIdx.x;
    const size_t total = (size_t)MROWS * 79;
    if (idx >= total) return;
    int c = (int)(idx % 79);
    int gr = (int)(idx / 79);
    int n = gr % NANCH;
    if (c < 2) {
        out_cls[(size_t)gr*2 + c] = g_head[(size_t)gr*75 + c];
    } else {
        int lc = c - 2;
        float v;
        if (lc < 4)       v = anchors[(size_t)n*77 + lc];
        else if (lc == 4) v = g_head[(size_t)gr*75 + 2];
        else              v = anchors[(size_t)n*77 + lc] + g_head[(size_t)gr*75 + lc - 2];
        out_lanes[(size_t)gr*77 + lc] = v;
    }
}

// ---------------- launch ----------------
extern "C" void kernel_launch(void* const* d_in, const int* in_sizes, int n_in,
                              void* d_out, int out_size) {
    const void* ptr[12];
    for (int i = 0; i < 12 && i < n_in; i++) ptr[i] = d_in[i];
    {
        int seen27840 = 0;
        for (int i = 0; i < n_in; i++) {
            switch (in_sizes[i]) {
                case 1024000: ptr[0]  = d_in[i]; break; // x
                case 32768:   ptr[1]  = d_in[i]; break; // conv_w
                case 64:      ptr[2]  = d_in[i]; break; // conv_b
                case 1781120: ptr[3]  = d_in[i]; break; // attn_w
                case 2783:    ptr[4]  = d_in[i]; break; // attn_b
                case 2560:    ptr[5]  = d_in[i]; break; // cls_w
                case 2:       ptr[6]  = d_in[i]; break; // cls_b
                case 93440:   ptr[7]  = d_in[i]; break; // reg_w
                case 73:      ptr[8]  = d_in[i]; break; // reg_b
                case 214368:  ptr[9]  = d_in[i]; break; // anchors
                case 27840:
                    if (seen27840 == 0) ptr[10] = d_in[i];
                    else                ptr[11] = d_in[i];
                    seen27840++;
                    break;
                default: break;
            }
        }
    }
    const float* x        = (const float*)ptr[0];
    const float* conv_w   = (const float*)ptr[1];
    const float* conv_b   = (const float*)ptr[2];
    const float* attn_w   = (const float*)ptr[3];
    const float* attn_b   = (const float*)ptr[4];
    const float* cls_w    = (const float*)ptr[5];
    const float* cls_b    = (const float*)ptr[6];
    const float* reg_w    = (const float*)ptr[7];
    const float* reg_b    = (const float*)ptr[8];
    const float* anchors  = (const float*)ptr[9];
    const int*   cut_xs   = (const int*)ptr[10];
    const void*  invalid  = ptr[11];

    float* out      = (float*)d_out;
    float* o_cls    = out;
    float* o_lanes  = out + (size_t)MROWS*2;
    float* o_attn   = out + (size_t)MROWS*79;

    __half *xh,*xl,*cwh,*cwl,*awh,*pfh,*pfl,*pth,*prh,*afh,*afl,*wh,*wl,*sc;
    float *b75,*head,*feat;
    cudaGetSymbolAddress((void**)&xh, g_xh);   cudaGetSymbolAddress((void**)&xl, g_xl);
    cudaGetSymbolAddress((void**)&cwh, g_cwh); cudaGetSymbolAddress((void**)&cwl, g_cwl);
    cudaGetSymbolAddress((void**)&awh, g_awh);
    cudaGetSymbolAddress((void**)&pfh, g_pfh); cudaGetSymbolAddress((void**)&pfl, g_pfl);
    cudaGetSymbolAddress((void**)&pth, g_pth);
    cudaGetSymbolAddress((void**)&prh, g_prh);
    cudaGetSymbolAddress((void**)&afh, g_afh); cudaGetSymbolAddress((void**)&afl, g_afl);
    cudaGetSymbolAddress((void**)&wh, g_wh);   cudaGetSymbolAddress((void**)&wl, g_wl);
    cudaGetSymbolAddress((void**)&b75, g_b75); cudaGetSymbolAddress((void**)&head, g_head);
    cudaGetSymbolAddress((void**)&feat, g_feat); cudaGetSymbolAddress((void**)&sc, g_sc);

    const int SMEM3 = 2 * 4 * TSH * 2;   // 81920  (3-pass, 2-stage, 256 thr)
    const int SMEM1 = 4 * 2 * TSH * 2;   // 81920  (1-pass, 4-stage, 128 thr)
    cudaFuncSetAttribute(k_hmma3<false>, cudaFuncAttributeMaxDynamicSharedMemorySize, SMEM3);
    cudaFuncSetAttribute(k_big<1>, cudaFuncAttributeMaxDynamicSharedMemorySize, SMEM1);
    cudaFuncSetAttribute(k_big<2>, cudaFuncAttributeMaxDynamicSharedMemorySize, SMEM1);

    // launch 0: fused prep
    k_prep<<<PREP_NB, 256>>>(x, conv_w, attn_w, cls_w, reg_w, cls_b, reg_b,
                             (const unsigned int*)invalid);

    // launch 1: conv (3-pass; pf accuracy feeds cls directly)
    k_hmma3<false><<<dim3(1, 16, 1), 256, SMEM3>>>(
        xh, xl, xh, xl, CIN, 1 << 28,
        cwh, cwl, CIN, CF,
        feat, conv_b,
        CF, BATCH*HW, CF, CIN/32);

    // launch 2: gather
    {
        size_t total = (size_t)BATCH*NANCH*DF;
        k_gather16<<<(unsigned)((total + 255)/256), 256>>>(cut_xs);
    }

    // launch 3 (ncu-captured): scores — 64x64 warp tiles, f16 out
    k_big<2><<<dim3(22, MROWS/128, 1), 128, SMEM1>>>(
        pfh, DF,
        awh, DF, MCOL,
        nullptr, sc, nullptr, attn_b,
        LDSC, MROWS, MCOL, DF/32, 0, 0, 0);

    // launch 4: softmax
    k_softmax<<<BATCH*NANCH, 256>>>(o_attn);

    // launch 5: pf transpose (hi only)
    k_pfT16<<<dim3(NANCH/32, DF/32, BATCH), dim3(32, 8)>>>();

    // launch 6: att_feats — 64x64 warp tiles, f16 hi/lo out
    k_big<1><<<dim3(5, 22, BATCH), 128, SMEM1>>>(
        prh, NANCH,
        pth, NANCH, DF,
        nullptr, afh, afl, nullptr,
        DF, NANCH, DF, NANCH/32,
        (size_t)NANCH*NANCH, (size_t)DF*NANCH, (size_t)NANCH*DF);

    // launch 7: head (3-pass, exact path for cls/reg)
    k_hmma3<false><<<dim3(1, MROWS/128, 1), 256, SMEM3>>>(
        afh, afl, pfh, pfl, DF, DF,
        wh, wl, KCAT, 75,
        head, b75,
        75, MROWS, 75, KCAT/32);

    // launch 8: finalize
    {
        size_t total = (size_t)MROWS * 79;
        k_finalize<<<(unsigned)((total + 255)/256), 256>>>(anchors, o_cls, o_lanes);
    }
}